// round 7
// baseline (speedup 1.0000x reference)
#include <cuda_runtime.h>
#include <cuda_fp16.h>
#include <cstdint>

#define D_MODEL 1024
#define NHEADS  16
#define HDIM    64
#define BATCH   2
#define SEQ     2048
#define NROWS   (BATCH * SEQ)     // 4096
#define KDIM    D_MODEL

// softmax scale folded into Q projection: 1/sqrt(64) * log2(e)
#define QK_SCALE 0.1803368801111244f

// ---------------------------------------------------------------------------
// Scratch (device globals) — all fp16 hi/lo pairs
// ---------------------------------------------------------------------------
__device__ __half g_Hhi [NROWS * D_MODEL];
__device__ __half g_Hlo [NROWS * D_MODEL];
__device__ __half g_Qh  [NROWS * D_MODEL];
__device__ __half g_Ql  [NROWS * D_MODEL];
__device__ __half g_Kh  [NROWS * D_MODEL];
__device__ __half g_Kl  [NROWS * D_MODEL];
__device__ __half g_AOh [NROWS * D_MODEL];
__device__ __half g_AOl [NROWS * D_MODEL];
__device__ __half g_Wqhi[D_MODEL * D_MODEL];
__device__ __half g_Wqlo[D_MODEL * D_MODEL];
__device__ __half g_Wkhi[D_MODEL * D_MODEL];
__device__ __half g_Wklo[D_MODEL * D_MODEL];
__device__ __half g_Wohi[D_MODEL * D_MODEL];
__device__ __half g_Wolo[D_MODEL * D_MODEL];

// ---------------------------------------------------------------------------
// helpers
// ---------------------------------------------------------------------------
__device__ __forceinline__ uint32_t smem_to_u32(const void* p) {
    uint32_t a;
    asm("{ .reg .u64 t; cvta.to.shared.u64 t, %1; cvt.u32.u64 %0, t; }"
        : "=r"(a) : "l"(p));
    return a;
}
__device__ __forceinline__ void ldsm_x4(uint32_t& r0, uint32_t& r1,
                                        uint32_t& r2, uint32_t& r3, uint32_t addr) {
    asm volatile("ldmatrix.sync.aligned.m8n8.x4.shared.b16 {%0,%1,%2,%3}, [%4];"
                 : "=r"(r0), "=r"(r1), "=r"(r2), "=r"(r3) : "r"(addr));
}
__device__ __forceinline__ void ldsm_x4_t(uint32_t& r0, uint32_t& r1,
                                          uint32_t& r2, uint32_t& r3, uint32_t addr) {
    asm volatile("ldmatrix.sync.aligned.m8n8.x4.trans.shared.b16 {%0,%1,%2,%3}, [%4];"
                 : "=r"(r0), "=r"(r1), "=r"(r2), "=r"(r3) : "r"(addr));
}
__device__ __forceinline__ void mma16816(float* c, const uint32_t* a,
                                         const uint32_t* b) {
    asm volatile(
        "mma.sync.aligned.m16n8k16.row.col.f32.f16.f16.f32 "
        "{%0,%1,%2,%3}, {%4,%5,%6,%7}, {%8,%9}, {%0,%1,%2,%3};"
        : "+f"(c[0]), "+f"(c[1]), "+f"(c[2]), "+f"(c[3])
        : "r"(a[0]), "r"(a[1]), "r"(a[2]), "r"(a[3]), "r"(b[0]), "r"(b[1]));
}
__device__ __forceinline__ float ex2f(float x) {
    float r;
    asm("ex2.approx.ftz.f32 %0, %1;" : "=f"(r) : "f"(x));
    return r;
}
__device__ __forceinline__ uint32_t packh2(float a, float b) {
    __half2 t = __floats2half2_rn(a, b);
    return *(uint32_t*)&t;
}
__device__ __forceinline__ void cp16(uint32_t smem, const void* g) {
    asm volatile("cp.async.cg.shared.global [%0], [%1], 16;"
                 :: "r"(smem), "l"(g) : "memory");
}
#define CP_COMMIT() asm volatile("cp.async.commit_group;" ::: "memory")
#define CP_WAIT0()  asm volatile("cp.async.wait_group 0;" ::: "memory")

// ---------------------------------------------------------------------------
// fp32 -> (fp16 hi, fp16 lo) split, 4 tensors in one launch
// ---------------------------------------------------------------------------
__device__ __forceinline__ void split4_do(const float4* src, uint2* hi, uint2* lo, int i)
{
    float4 v = src[i];
    __half h0 = __float2half_rn(v.x), h1 = __float2half_rn(v.y);
    __half h2 = __float2half_rn(v.z), h3 = __float2half_rn(v.w);
    float r0 = v.x - __half2float(h0), r1 = v.y - __half2float(h1);
    float r2 = v.z - __half2float(h2), r3 = v.w - __half2float(h3);
    hi[i] = make_uint2(
        (uint32_t)__half_as_ushort(h0) | ((uint32_t)__half_as_ushort(h1) << 16),
        (uint32_t)__half_as_ushort(h2) | ((uint32_t)__half_as_ushort(h3) << 16));
    lo[i] = make_uint2(packh2(r0, r1), packh2(r2, r3));
}

__global__ __launch_bounds__(256)
void split4_kernel(const float4* s0, uint2* h0, uint2* l0, int n0,
                   const float4* s1, uint2* h1, uint2* l1, int n1,
                   const float4* s2, uint2* h2, uint2* l2, int n2,
                   const float4* s3, uint2* h3, uint2* l3, int n3)
{
    int i = blockIdx.x * blockDim.x + threadIdx.x;
    if (i < n0) { split4_do(s0, h0, l0, i); return; }
    i -= n0;
    if (i < n1) { split4_do(s1, h1, l1, i); return; }
    i -= n1;
    if (i < n2) { split4_do(s2, h2, l2, i); return; }
    i -= n2;
    if (i < n3) { split4_do(s3, h3, l3, i); }
}

// ---------------------------------------------------------------------------
// HMMA GEMM, cp.async double-buffered, fp16 3-pass split (pass-outer order).
// C[4096,1024] = A @ W^T + bias. CTA 128x128, BK=32, 256 threads (8 warps).
// ---------------------------------------------------------------------------
#define BM 128
#define BN 128
#define BKK 32
#define LDT 40                     // 80 B row (5 x 16B) -> LDSM conflict-free
#define GTILE (BM * LDT * 2)       // 10240 B
#define GST   (4 * GTILE)          // 40960 B per stage
#define GNIT  (KDIM / BKK)         // 32

__device__ __forceinline__ void gemm_core(
    const __half* __restrict__ Ahi, const __half* __restrict__ Alo,
    const __half* __restrict__ Whi, const __half* __restrict__ Wlo,
    const float* __restrict__ bias, float scale,
    float* __restrict__ Cf, __half* __restrict__ Ch, __half* __restrict__ Cl)
{
    extern __shared__ char dsm[];
    __shared__ float s_bias[BN];

    const int tid = threadIdx.x;
    const int wid = tid >> 5;
    const int lid = tid & 31;
    const int wm  = wid & 1;
    const int wn  = wid >> 1;
    const int m0  = blockIdx.y * BM;
    const int n0  = blockIdx.x * BN;

    if (tid < BN) s_bias[tid] = bias[n0 + tid];

    const int lr   = lid & 7;
    const int half2_ = (lid >> 3) & 1;
    const int kh   = (lid >> 4) & 1;
    const int mbase = wm * 64;
    const int nbase = wn * 32;

    const uint32_t smem_base = smem_to_u32(dsm);

    float acc[4][4][4];
#pragma unroll
    for (int i = 0; i < 4; i++)
#pragma unroll
        for (int j = 0; j < 4; j++)
#pragma unroll
            for (int c = 0; c < 4; c++) acc[i][j][c] = 0.0f;

    auto load_stage = [&](int k0, int s) {
        uint32_t sb = smem_base + s * GST;
#pragma unroll
        for (int it = 0; it < 8; it++) {
            int tile = it >> 1;
            int rem  = ((it & 1) << 8) + tid;
            int row  = rem >> 2;
            int c    = rem & 3;
            const __half* g;
            if (tile == 0)      g = Ahi + (size_t)(m0 + row) * KDIM + k0 + c * 8;
            else if (tile == 1) g = Alo + (size_t)(m0 + row) * KDIM + k0 + c * 8;
            else if (tile == 2) g = Whi + (size_t)(n0 + row) * KDIM + k0 + c * 8;
            else                g = Wlo + (size_t)(n0 + row) * KDIM + k0 + c * 8;
            cp16(sb + tile * GTILE + row * (LDT * 2) + c * 16, g);
        }
        CP_COMMIT();
    };

    load_stage(0, 0);

    for (int i = 0; i < GNIT; i++) {
        const int s = i & 1;
        CP_WAIT0();
        __syncthreads();
        if (i + 1 < GNIT) load_stage((i + 1) * BKK, s ^ 1);

        const uint32_t sb   = smem_base + s * GST;
        const uint32_t uAhi = sb;
        const uint32_t uAlo = sb + GTILE;
        const uint32_t uWhi = sb + 2 * GTILE;
        const uint32_t uWlo = sb + 3 * GTILE;

#pragma unroll
        for (int ks = 0; ks < 2; ks++) {
            const int kcol = ks * 16 + kh * 8;

            uint32_t ahi[4][4], alo[4][4];
#pragma unroll
            for (int mt = 0; mt < 4; mt++) {
                int row = mbase + mt * 16 + lr + 8 * half2_;
                ldsm_x4(ahi[mt][0], ahi[mt][1], ahi[mt][2], ahi[mt][3],
                        uAhi + (uint32_t)(row * LDT + kcol) * 2);
                ldsm_x4(alo[mt][0], alo[mt][1], alo[mt][2], alo[mt][3],
                        uAlo + (uint32_t)(row * LDT + kcol) * 2);
            }
            uint32_t bhi[4][2], blo[4][2];
#pragma unroll
            for (int ntp = 0; ntp < 2; ntp++) {
                int row = nbase + ntp * 16 + lr + 8 * half2_;
                uint32_t r0, r1, r2, r3;
                ldsm_x4(r0, r1, r2, r3, uWhi + (uint32_t)(row * LDT + kcol) * 2);
                bhi[ntp * 2 + 0][0] = r0; bhi[ntp * 2 + 0][1] = r2;
                bhi[ntp * 2 + 1][0] = r1; bhi[ntp * 2 + 1][1] = r3;
                ldsm_x4(r0, r1, r2, r3, uWlo + (uint32_t)(row * LDT + kcol) * 2);
                blo[ntp * 2 + 0][0] = r0; blo[ntp * 2 + 0][1] = r2;
                blo[ntp * 2 + 1][0] = r1; blo[ntp * 2 + 1][1] = r3;
            }
            // pass-outer: 16 independent accumulators between revisits
#pragma unroll
            for (int mt = 0; mt < 4; mt++)
#pragma unroll
                for (int nt = 0; nt < 4; nt++)
                    mma16816(acc[mt][nt], ahi[mt], bhi[nt]);
#pragma unroll
            for (int mt = 0; mt < 4; mt++)
#pragma unroll
                for (int nt = 0; nt < 4; nt++)
                    mma16816(acc[mt][nt], ahi[mt], blo[nt]);
#pragma unroll
            for (int mt = 0; mt < 4; mt++)
#pragma unroll
                for (int nt = 0; nt < 4; nt++)
                    mma16816(acc[mt][nt], alo[mt], bhi[nt]);
        }
    }

    const int erow = lid >> 2;
    const int ecol = (lid & 3) * 2;
#pragma unroll
    for (int mt = 0; mt < 4; mt++) {
#pragma unroll
        for (int nt = 0; nt < 4; nt++) {
            int gm = m0 + mbase + mt * 16 + erow;
            int nc = nbase + nt * 8 + ecol;
            int gn = n0 + nc;
            float v0 = (acc[mt][nt][0] + s_bias[nc])     * scale;
            float v1 = (acc[mt][nt][1] + s_bias[nc + 1]) * scale;
            float v2 = (acc[mt][nt][2] + s_bias[nc])     * scale;
            float v3 = (acc[mt][nt][3] + s_bias[nc + 1]) * scale;
            if (Ch) {
                __half h0 = __float2half_rn(v0), h1 = __float2half_rn(v1);
                __half h2 = __float2half_rn(v2), h3 = __float2half_rn(v3);
                *(uint32_t*)&Ch[(size_t)gm * D_MODEL + gn] =
                    (uint32_t)__half_as_ushort(h0) | ((uint32_t)__half_as_ushort(h1) << 16);
                *(uint32_t*)&Cl[(size_t)gm * D_MODEL + gn] =
                    packh2(v0 - __half2float(h0), v1 - __half2float(h1));
                *(uint32_t*)&Ch[(size_t)(gm + 8) * D_MODEL + gn] =
                    (uint32_t)__half_as_ushort(h2) | ((uint32_t)__half_as_ushort(h3) << 16);
                *(uint32_t*)&Cl[(size_t)(gm + 8) * D_MODEL + gn] =
                    packh2(v2 - __half2float(h2), v3 - __half2float(h3));
            } else {
                *(float2*)&Cf[(size_t)gm * D_MODEL + gn]       = make_float2(v0, v1);
                *(float2*)&Cf[(size_t)(gm + 8) * D_MODEL + gn] = make_float2(v2, v3);
            }
        }
    }
}

__global__ __launch_bounds__(256, 2)
void qk_gemm_kernel(const float* __restrict__ bq, const float* __restrict__ bk)
{
    if (blockIdx.z == 0)
        gemm_core(g_Hhi, g_Hlo, g_Wqhi, g_Wqlo, bq, QK_SCALE, nullptr, g_Qh, g_Ql);
    else
        gemm_core(g_Hhi, g_Hlo, g_Wkhi, g_Wklo, bk, 1.0f, nullptr, g_Kh, g_Kl);
}

__global__ __launch_bounds__(256, 2)
void out_gemm_kernel(const float* __restrict__ bo, float* __restrict__ out)
{
    gemm_core(g_AOh, g_AOl, g_Wohi, g_Wolo, bo, 1.0f, out, nullptr, nullptr);
}

// ---------------------------------------------------------------------------
// HMMA flash attention, fp16: QK^T 3-pass, PV 2-pass (pass-outer order).
// grid (32 = B*NH, 16 = SEQ/128), 256 threads (8 warps), 128 q-rows per CTA.
// ---------------------------------------------------------------------------
#define SLDT 72                        // 144 B row (9 x 16B)
#define ATILE (64 * SLDT * 2)          // 9216 B per array
#define AST   (4 * ATILE)              // 36864 B per stage

__global__ __launch_bounds__(256, 1)
void attn_mma_kernel()
{
    extern __shared__ char dsm[];
    __half* pool = (__half*)dsm;

    const int tid = threadIdx.x;
    const int wid = tid >> 5;
    const int lid = tid & 31;
    const int b   = blockIdx.x >> 4;
    const int h   = blockIdx.x & 15;
    const int q0  = blockIdx.y * 128;

    const int lr    = lid & 7;
    const int half2_ = (lid >> 3) & 1;
    const int kh    = (lid >> 4) & 1;

    const uint32_t smem_base = smem_to_u32(dsm);

    // ---- stage Q tile (128 x 64, hi/lo) through stage-0 area, extract frags ----
#pragma unroll
    for (int i = 0; i < 8; i++) {
        int e   = tid + i * 256;
        int arr = e >> 10;
        int rem = e & 1023;
        int row = rem >> 3;
        int c   = rem & 7;
        const __half* src = (arr ? g_Ql : g_Qh)
            + (size_t)(b * SEQ + q0 + row) * D_MODEL + h * HDIM + c * 8;
        *(uint4*)(pool + arr * 128 * SLDT + row * SLDT + c * 8) = *(const uint4*)src;
    }
    __syncthreads();

    uint32_t qh[4][4], ql[4][4];
    {
        const int wr = wid * 16;
        const uint32_t uQh = smem_base;
        const uint32_t uQl = smem_base + 128 * SLDT * 2;
#pragma unroll
        for (int kc = 0; kc < 4; kc++) {
            int row = wr + lr + 8 * half2_;
            int col = kc * 16 + kh * 8;
            ldsm_x4(qh[kc][0], qh[kc][1], qh[kc][2], qh[kc][3],
                    uQh + (uint32_t)(row * SLDT + col) * 2);
            ldsm_x4(ql[kc][0], ql[kc][1], ql[kc][2], ql[kc][3],
                    uQl + (uint32_t)(row * SLDT + col) * 2);
        }
    }
    __syncthreads();

    float oacc[8][4];
#pragma unroll
    for (int nt = 0; nt < 8; nt++)
#pragma unroll
        for (int c = 0; c < 4; c++) oacc[nt][c] = 0.0f;
    float mx0 = -1e30f, mx1 = -1e30f, l0 = 0.0f, l1 = 0.0f;

    auto load_stage = [&](int kt, int s) {
        const int kb = kt * 64;
        uint32_t sb = smem_base + s * AST;
#pragma unroll
        for (int i = 0; i < 8; i++) {
            int arr = i >> 1;
            int rem = ((i & 1) << 8) + tid;
            int row = rem >> 3;
            int c   = rem & 7;
            const __half* g =
                (arr == 0 ? g_Kh : arr == 1 ? g_Kl : arr == 2 ? g_Hhi : g_Hlo)
                + (size_t)(b * SEQ + kb + row) * D_MODEL + h * HDIM + c * 8;
            cp16(sb + arr * ATILE + row * (SLDT * 2) + c * 16, g);
        }
        CP_COMMIT();
    };

    load_stage(0, 0);

    for (int kt = 0; kt < SEQ / 64; kt++) {
        const int s = kt & 1;
        CP_WAIT0();
        __syncthreads();
        if (kt + 1 < SEQ / 64) load_stage(kt + 1, s ^ 1);

        const uint32_t sb  = smem_base + s * AST;
        const uint32_t uKh = sb;
        const uint32_t uKl = sb + ATILE;
        const uint32_t uVh = sb + 2 * ATILE;
        const uint32_t uVl = sb + 3 * ATILE;

        // ---- S = Q K^T (3-pass fp16, pass-outer over 8 S-tiles) ----
        float S[8][4];
#pragma unroll
        for (int nt = 0; nt < 8; nt++)
#pragma unroll
            for (int c = 0; c < 4; c++) S[nt][c] = 0.0f;

#pragma unroll
        for (int kc = 0; kc < 4; kc++) {
            uint32_t kbh[8][2], kbl[8][2];
#pragma unroll
            for (int ng = 0; ng < 4; ng++) {
                int row = ng * 16 + lr + 8 * half2_;
                int col = kc * 16 + kh * 8;
                uint32_t r0, r1, r2, r3;
                ldsm_x4(r0, r1, r2, r3, uKh + (uint32_t)(row * SLDT + col) * 2);
                kbh[ng * 2 + 0][0] = r0; kbh[ng * 2 + 0][1] = r2;
                kbh[ng * 2 + 1][0] = r1; kbh[ng * 2 + 1][1] = r3;
                ldsm_x4(r0, r1, r2, r3, uKl + (uint32_t)(row * SLDT + col) * 2);
                kbl[ng * 2 + 0][0] = r0; kbl[ng * 2 + 0][1] = r2;
                kbl[ng * 2 + 1][0] = r1; kbl[ng * 2 + 1][1] = r3;
            }
#pragma unroll
            for (int nt = 0; nt < 8; nt++)
                mma16816(S[nt], qh[kc], kbh[nt]);
#pragma unroll
            for (int nt = 0; nt < 8; nt++)
                mma16816(S[nt], qh[kc], kbl[nt]);
#pragma unroll
            for (int nt = 0; nt < 8; nt++)
                mma16816(S[nt], ql[kc], kbh[nt]);
        }

        // ---- online softmax ----
        float tm0 = -1e30f, tm1 = -1e30f;
#pragma unroll
        for (int nt = 0; nt < 8; nt++) {
            tm0 = fmaxf(tm0, fmaxf(S[nt][0], S[nt][1]));
            tm1 = fmaxf(tm1, fmaxf(S[nt][2], S[nt][3]));
        }
        tm0 = fmaxf(tm0, __shfl_xor_sync(0xffffffffu, tm0, 1));
        tm0 = fmaxf(tm0, __shfl_xor_sync(0xffffffffu, tm0, 2));
        tm1 = fmaxf(tm1, __shfl_xor_sync(0xffffffffu, tm1, 1));
        tm1 = fmaxf(tm1, __shfl_xor_sync(0xffffffffu, tm1, 2));
        float mn0 = fmaxf(mx0, tm0), mn1 = fmaxf(mx1, tm1);
        float a0 = ex2f(mx0 - mn0), a1 = ex2f(mx1 - mn1);

        // ---- P (single fp16 fragments) ----
        uint32_t pa[4][4];
        float rs0 = 0.0f, rs1 = 0.0f;
#pragma unroll
        for (int j = 0; j < 4; j++) {
#pragma unroll
            for (int sg = 0; sg < 2; sg++) {
                int t2 = j * 2 + sg;
                float p0 = ex2f(S[t2][0] - mn0);
                float p1 = ex2f(S[t2][1] - mn0);
                float p2 = ex2f(S[t2][2] - mn1);
                float p3 = ex2f(S[t2][3] - mn1);
                rs0 += p0 + p1;
                rs1 += p2 + p3;
                pa[j][sg * 2 + 0] = packh2(p0, p1);
                pa[j][sg * 2 + 1] = packh2(p2, p3);
            }
        }
        rs0 += __shfl_xor_sync(0xffffffffu, rs0, 1);
        rs0 += __shfl_xor_sync(0xffffffffu, rs0, 2);
        rs1 += __shfl_xor_sync(0xffffffffu, rs1, 1);
        rs1 += __shfl_xor_sync(0xffffffffu, rs1, 2);
        l0 = l0 * a0 + rs0;
        l1 = l1 * a1 + rs1;
        mx0 = mn0; mx1 = mn1;
#pragma unroll
        for (int nt = 0; nt < 8; nt++) {
            oacc[nt][0] *= a0; oacc[nt][1] *= a0;
            oacc[nt][2] *= a1; oacc[nt][3] *= a1;
        }

        // ---- O += P V (2-pass, pass-outer over 8 O-tiles) ----
#pragma unroll
        for (int kc = 0; kc < 4; kc++) {
            uint32_t vbh[8][2], vbl[8][2];
#pragma unroll
            for (int dg = 0; dg < 4; dg++) {
                int rowk = kc * 16 + lr + 8 * half2_;
                int dimc = dg * 16 + kh * 8;
                uint32_t r0, r1, r2, r3;
                ldsm_x4_t(r0, r1, r2, r3, uVh + (uint32_t)(rowk * SLDT + dimc) * 2);
                vbh[dg * 2 + 0][0] = r0; vbh[dg * 2 + 0][1] = r1;
                vbh[dg * 2 + 1][0] = r2; vbh[dg * 2 + 1][1] = r3;
                ldsm_x4_t(r0, r1, r2, r3, uVl + (uint32_t)(rowk * SLDT + dimc) * 2);
                vbl[dg * 2 + 0][0] = r0; vbl[dg * 2 + 0][1] = r1;
                vbl[dg * 2 + 1][0] = r2; vbl[dg * 2 + 1][1] = r3;
            }
#pragma unroll
            for (int nt = 0; nt < 8; nt++)
                mma16816(oacc[nt], pa[kc], vbh[nt]);
#pragma unroll
            for (int nt = 0; nt < 8; nt++)
                mma16816(oacc[nt], pa[kc], vbl[nt]);
        }
    }

    // ---- epilogue: normalize, fp16 hi/lo split, store ----
    const float inv0 = 1.0f / l0;
    const float inv1 = 1.0f / l1;
    const int gr  = b * SEQ + q0 + wid * 16 + (lid >> 2);
    const int col = h * HDIM + (lid & 3) * 2;
#pragma unroll
    for (int nt = 0; nt < 8; nt++) {
        int gc = col + nt * 8;
        float v0 = oacc[nt][0] * inv0, v1 = oacc[nt][1] * inv0;
        float v2 = oacc[nt][2] * inv1, v3 = oacc[nt][3] * inv1;
        __half h0 = __float2half_rn(v0), h1 = __float2half_rn(v1);
        __half h2 = __float2half_rn(v2), h3 = __float2half_rn(v3);
        *(uint32_t*)&g_AOh[(size_t)gr * D_MODEL + gc] =
            (uint32_t)__half_as_ushort(h0) | ((uint32_t)__half_as_ushort(h1) << 16);
        *(uint32_t*)&g_AOl[(size_t)gr * D_MODEL + gc] =
            packh2(v0 - __half2float(h0), v1 - __half2float(h1));
        *(uint32_t*)&g_AOh[(size_t)(gr + 8) * D_MODEL + gc] =
            (uint32_t)__half_as_ushort(h2) | ((uint32_t)__half_as_ushort(h3) << 16);
        *(uint32_t*)&g_AOl[(size_t)(gr + 8) * D_MODEL + gc] =
            packh2(v2 - __half2float(h2), v3 - __half2float(h3));
    }
}

// ---------------------------------------------------------------------------
extern "C" void kernel_launch(void* const* d_in, const int* in_sizes, int n_in,
                              void* d_out, int out_size)
{
    (void)in_sizes; (void)n_in; (void)out_size;
    const float* H  = (const float*)d_in[0];
    const float* Wq = (const float*)d_in[1];
    const float* bq = (const float*)d_in[2];
    const float* Wk = (const float*)d_in[3];
    const float* bk = (const float*)d_in[4];
    const float* Wo = (const float*)d_in[5];
    const float* bo = (const float*)d_in[6];
    float* out = (float*)d_out;

    void *p_Hhi, *p_Hlo;
    void *p_Wqhi, *p_Wqlo, *p_Wkhi, *p_Wklo, *p_Wohi, *p_Wolo;
    cudaGetSymbolAddress(&p_Hhi,  g_Hhi);  cudaGetSymbolAddress(&p_Hlo,  g_Hlo);
    cudaGetSymbolAddress(&p_Wqhi, g_Wqhi); cudaGetSymbolAddress(&p_Wqlo, g_Wqlo);
    cudaGetSymbolAddress(&p_Wkhi, g_Wkhi); cudaGetSymbolAddress(&p_Wklo, g_Wklo);
    cudaGetSymbolAddress(&p_Wohi, g_Wohi); cudaGetSymbolAddress(&p_Wolo, g_Wolo);

    cudaFuncSetAttribute(qk_gemm_kernel,
                         cudaFuncAttributeMaxDynamicSharedMemorySize, 2 * GST);
    cudaFuncSetAttribute(out_gemm_kernel,
                         cudaFuncAttributeMaxDynamicSharedMemorySize, 2 * GST);
    cudaFuncSetAttribute(attn_mma_kernel,
                         cudaFuncAttributeMaxDynamicSharedMemorySize, 2 * AST);

    const int nH4 = NROWS * D_MODEL / 4;      // 1,048,576
    const int nW4 = D_MODEL * D_MODEL / 4;    // 262,144
    const int nTot = nH4 + 3 * nW4;           // 1,835,008

    split4_kernel<<<(nTot + 255) / 256, 256>>>(
        (const float4*)H,  (uint2*)p_Hhi,  (uint2*)p_Hlo,  nH4,
        (const float4*)Wq, (uint2*)p_Wqhi, (uint2*)p_Wqlo, nW4,
        (const float4*)Wk, (uint2*)p_Wkhi, (uint2*)p_Wklo, nW4,
        (const float4*)Wo, (uint2*)p_Wohi, (uint2*)p_Wolo, nW4);

    dim3 ggrid(D_MODEL / BN, NROWS / BM, 2);   // (8, 32, 2)
    qk_gemm_kernel<<<ggrid, 256, 2 * GST>>>(bq, bk);

    dim3 agrid(BATCH * NHEADS, SEQ / 128);     // (32, 16)
    attn_mma_kernel<<<agrid, 256, 2 * AST>>>();

    dim3 ogrid(D_MODEL / BN, NROWS / BM, 1);   // (8, 32)
    out_gemm_kernel<<<ogrid, 256, 2 * GST>>>(bo, out);
}

// round 8
// speedup vs baseline: 1.1972x; 1.1972x over previous
#include <cuda_runtime.h>
#include <cuda_fp16.h>
#include <cstdint>

#define D_MODEL 1024
#define NHEADS  16
#define HDIM    64
#define BATCH   2
#define SEQ     2048
#define NROWS   (BATCH * SEQ)     // 4096
#define KDIM    D_MODEL

// softmax scale folded into Q projection: 1/sqrt(64) * log2(e)
#define QK_SCALE 0.1803368801111244f

// ---------------------------------------------------------------------------
// Scratch (device globals)
// ---------------------------------------------------------------------------
__device__ __half g_Hhi [NROWS * D_MODEL];
__device__ __half g_Hlo [NROWS * D_MODEL];   // used as V-lo in attention
__device__ __half g_Qh  [NROWS * D_MODEL];
__device__ __half g_Ql  [NROWS * D_MODEL];
__device__ __half g_Kh  [NROWS * D_MODEL];
__device__ __half g_Kl  [NROWS * D_MODEL];
__device__ __half g_AOh [NROWS * D_MODEL];
__device__ __half g_Wqhi[D_MODEL * D_MODEL];
__device__ __half g_Wqlo[D_MODEL * D_MODEL];
__device__ __half g_Wkhi[D_MODEL * D_MODEL];
__device__ __half g_Wklo[D_MODEL * D_MODEL];
__device__ __half g_Wohi[D_MODEL * D_MODEL];
__device__ __half g_Wolo[D_MODEL * D_MODEL];

// ---------------------------------------------------------------------------
// helpers
// ---------------------------------------------------------------------------
__device__ __forceinline__ uint32_t smem_to_u32(const void* p) {
    uint32_t a;
    asm("{ .reg .u64 t; cvta.to.shared.u64 t, %1; cvt.u32.u64 %0, t; }"
        : "=r"(a) : "l"(p));
    return a;
}
__device__ __forceinline__ void ldsm_x4(uint32_t& r0, uint32_t& r1,
                                        uint32_t& r2, uint32_t& r3, uint32_t addr) {
    asm volatile("ldmatrix.sync.aligned.m8n8.x4.shared.b16 {%0,%1,%2,%3}, [%4];"
                 : "=r"(r0), "=r"(r1), "=r"(r2), "=r"(r3) : "r"(addr));
}
__device__ __forceinline__ void ldsm_x4_t(uint32_t& r0, uint32_t& r1,
                                          uint32_t& r2, uint32_t& r3, uint32_t addr) {
    asm volatile("ldmatrix.sync.aligned.m8n8.x4.trans.shared.b16 {%0,%1,%2,%3}, [%4];"
                 : "=r"(r0), "=r"(r1), "=r"(r2), "=r"(r3) : "r"(addr));
}
__device__ __forceinline__ void mma16816(float* c, const uint32_t* a,
                                         const uint32_t* b) {
    asm volatile(
        "mma.sync.aligned.m16n8k16.row.col.f32.f16.f16.f32 "
        "{%0,%1,%2,%3}, {%4,%5,%6,%7}, {%8,%9}, {%0,%1,%2,%3};"
        : "+f"(c[0]), "+f"(c[1]), "+f"(c[2]), "+f"(c[3])
        : "r"(a[0]), "r"(a[1]), "r"(a[2]), "r"(a[3]), "r"(b[0]), "r"(b[1]));
}
__device__ __forceinline__ float ex2f(float x) {
    float r;
    asm("ex2.approx.ftz.f32 %0, %1;" : "=f"(r) : "f"(x));
    return r;
}
__device__ __forceinline__ uint32_t packh2(float a, float b) {
    __half2 t = __floats2half2_rn(a, b);
    return *(uint32_t*)&t;
}
__device__ __forceinline__ void cp16(uint32_t smem, const void* g) {
    asm volatile("cp.async.cg.shared.global [%0], [%1], 16;"
                 :: "r"(smem), "l"(g) : "memory");
}
#define CP_COMMIT() asm volatile("cp.async.commit_group;" ::: "memory")
#define CP_WAIT0()  asm volatile("cp.async.wait_group 0;" ::: "memory")

// ---------------------------------------------------------------------------
// fp32 -> (fp16 hi, fp16 lo) split, 4 tensors in one launch
// ---------------------------------------------------------------------------
__device__ __forceinline__ void split4_do(const float4* src, uint2* hi, uint2* lo, int i)
{
    float4 v = src[i];
    __half h0 = __float2half_rn(v.x), h1 = __float2half_rn(v.y);
    __half h2 = __float2half_rn(v.z), h3 = __float2half_rn(v.w);
    float r0 = v.x - __half2float(h0), r1 = v.y - __half2float(h1);
    float r2 = v.z - __half2float(h2), r3 = v.w - __half2float(h3);
    hi[i] = make_uint2(
        (uint32_t)__half_as_ushort(h0) | ((uint32_t)__half_as_ushort(h1) << 16),
        (uint32_t)__half_as_ushort(h2) | ((uint32_t)__half_as_ushort(h3) << 16));
    lo[i] = make_uint2(packh2(r0, r1), packh2(r2, r3));
}

__global__ __launch_bounds__(256)
void split4_kernel(const float4* s0, uint2* h0, uint2* l0, int n0,
                   const float4* s1, uint2* h1, uint2* l1, int n1,
                   const float4* s2, uint2* h2, uint2* l2, int n2,
                   const float4* s3, uint2* h3, uint2* l3, int n3)
{
    int i = blockIdx.x * blockDim.x + threadIdx.x;
    if (i < n0) { split4_do(s0, h0, l0, i); return; }
    i -= n0;
    if (i < n1) { split4_do(s1, h1, l1, i); return; }
    i -= n1;
    if (i < n2) { split4_do(s2, h2, l2, i); return; }
    i -= n2;
    if (i < n3) { split4_do(s3, h3, l3, i); }
}

// ---------------------------------------------------------------------------
// HMMA GEMM, 2-pass split: C = Ahi*(Whi + Wlo) + bias.
// CTA 128x128, BK=64, 256 threads (8 warps), 1 CTA/SM, cp.async double-buffer.
// ---------------------------------------------------------------------------
#define BM 128
#define BN 128
#define BKK 64
#define LDT 72                     // 144 B row (9 x 16B) -> LDSM conflict-free
#define GTILE (BM * LDT * 2)       // 18432 B per array
#define GST   (3 * GTILE)          // 55296 B per stage (Ahi, Whi, Wlo)
#define GNIT  (KDIM / BKK)         // 16

__device__ __forceinline__ void gemm_core(
    const __half* __restrict__ Ahi,
    const __half* __restrict__ Whi, const __half* __restrict__ Wlo,
    const float* __restrict__ bias, float scale,
    float* __restrict__ Cf, __half* __restrict__ Ch, __half* __restrict__ Cl)
{
    extern __shared__ char dsm[];
    __shared__ float s_bias[BN];

    const int tid = threadIdx.x;
    const int wid = tid >> 5;
    const int lid = tid & 31;
    const int wm  = wid & 1;
    const int wn  = wid >> 1;
    const int m0  = blockIdx.y * BM;
    const int n0  = blockIdx.x * BN;

    if (tid < BN) s_bias[tid] = bias[n0 + tid];

    const int lr     = lid & 7;
    const int half2_ = (lid >> 3) & 1;
    const int kh     = (lid >> 4) & 1;
    const int mbase  = wm * 64;
    const int nbase  = wn * 32;

    const uint32_t smem_base = smem_to_u32(dsm);

    float acc[4][4][4];
#pragma unroll
    for (int i = 0; i < 4; i++)
#pragma unroll
        for (int j = 0; j < 4; j++)
#pragma unroll
            for (int c = 0; c < 4; c++) acc[i][j][c] = 0.0f;

    // stage = 3 arrays x 128 rows x 64 cols fp16; 1024 chunks(16B)/array
    auto load_stage = [&](int k0, int s) {
        uint32_t sb = smem_base + s * GST;
#pragma unroll
        for (int it = 0; it < 12; it++) {
            int e    = tid + it * 256;      // 0..3071
            int arr  = e >> 10;             // 0 Ahi, 1 Whi, 2 Wlo
            int rem  = e & 1023;
            int row  = rem >> 3;
            int c    = rem & 7;
            const __half* g;
            if (arr == 0)      g = Ahi + (size_t)(m0 + row) * KDIM + k0 + c * 8;
            else if (arr == 1) g = Whi + (size_t)(n0 + row) * KDIM + k0 + c * 8;
            else               g = Wlo + (size_t)(n0 + row) * KDIM + k0 + c * 8;
            cp16(sb + arr * GTILE + row * (LDT * 2) + c * 16, g);
        }
        CP_COMMIT();
    };

    load_stage(0, 0);

    for (int i = 0; i < GNIT; i++) {
        const int s = i & 1;
        CP_WAIT0();
        __syncthreads();
        if (i + 1 < GNIT) load_stage((i + 1) * BKK, s ^ 1);

        const uint32_t sb   = smem_base + s * GST;
        const uint32_t uAhi = sb;
        const uint32_t uWhi = sb + GTILE;
        const uint32_t uWlo = sb + 2 * GTILE;

#pragma unroll
        for (int ks = 0; ks < 4; ks++) {
            const int kcol = ks * 16 + kh * 8;

            uint32_t ahi[4][4];
#pragma unroll
            for (int mt = 0; mt < 4; mt++) {
                int row = mbase + mt * 16 + lr + 8 * half2_;
                ldsm_x4(ahi[mt][0], ahi[mt][1], ahi[mt][2], ahi[mt][3],
                        uAhi + (uint32_t)(row * LDT + kcol) * 2);
            }
            uint32_t bhi[4][2], blo[4][2];
#pragma unroll
            for (int ntp = 0; ntp < 2; ntp++) {
                int row = nbase + ntp * 16 + lr + 8 * half2_;
                uint32_t r0, r1, r2, r3;
                ldsm_x4(r0, r1, r2, r3, uWhi + (uint32_t)(row * LDT + kcol) * 2);
                bhi[ntp * 2 + 0][0] = r0; bhi[ntp * 2 + 0][1] = r2;
                bhi[ntp * 2 + 1][0] = r1; bhi[ntp * 2 + 1][1] = r3;
                ldsm_x4(r0, r1, r2, r3, uWlo + (uint32_t)(row * LDT + kcol) * 2);
                blo[ntp * 2 + 0][0] = r0; blo[ntp * 2 + 0][1] = r2;
                blo[ntp * 2 + 1][0] = r1; blo[ntp * 2 + 1][1] = r3;
            }
#pragma unroll
            for (int mt = 0; mt < 4; mt++)
#pragma unroll
                for (int nt = 0; nt < 4; nt++)
                    mma16816(acc[mt][nt], ahi[mt], bhi[nt]);
#pragma unroll
            for (int mt = 0; mt < 4; mt++)
#pragma unroll
                for (int nt = 0; nt < 4; nt++)
                    mma16816(acc[mt][nt], ahi[mt], blo[nt]);
        }
    }

    const int erow = lid >> 2;
    const int ecol = (lid & 3) * 2;
#pragma unroll
    for (int mt = 0; mt < 4; mt++) {
#pragma unroll
        for (int nt = 0; nt < 4; nt++) {
            int gm = m0 + mbase + mt * 16 + erow;
            int nc = nbase + nt * 8 + ecol;
            int gn = n0 + nc;
            float v0 = (acc[mt][nt][0] + s_bias[nc])     * scale;
            float v1 = (acc[mt][nt][1] + s_bias[nc + 1]) * scale;
            float v2 = (acc[mt][nt][2] + s_bias[nc])     * scale;
            float v3 = (acc[mt][nt][3] + s_bias[nc + 1]) * scale;
            if (Ch) {
                __half h0 = __float2half_rn(v0), h1 = __float2half_rn(v1);
                __half h2 = __float2half_rn(v2), h3 = __float2half_rn(v3);
                *(uint32_t*)&Ch[(size_t)gm * D_MODEL + gn] =
                    (uint32_t)__half_as_ushort(h0) | ((uint32_t)__half_as_ushort(h1) << 16);
                *(uint32_t*)&Cl[(size_t)gm * D_MODEL + gn] =
                    packh2(v0 - __half2float(h0), v1 - __half2float(h1));
                *(uint32_t*)&Ch[(size_t)(gm + 8) * D_MODEL + gn] =
                    (uint32_t)__half_as_ushort(h2) | ((uint32_t)__half_as_ushort(h3) << 16);
                *(uint32_t*)&Cl[(size_t)(gm + 8) * D_MODEL + gn] =
                    packh2(v2 - __half2float(h2), v3 - __half2float(h3));
            } else {
                *(float2*)&Cf[(size_t)gm * D_MODEL + gn]       = make_float2(v0, v1);
                *(float2*)&Cf[(size_t)(gm + 8) * D_MODEL + gn] = make_float2(v2, v3);
            }
        }
    }
}

__global__ __launch_bounds__(256, 1)
void qk_gemm_kernel(const float* __restrict__ bq, const float* __restrict__ bk)
{
    if (blockIdx.z == 0)
        gemm_core(g_Hhi, g_Wqhi, g_Wqlo, bq, QK_SCALE, nullptr, g_Qh, g_Ql);
    else
        gemm_core(g_Hhi, g_Wkhi, g_Wklo, bk, 1.0f, nullptr, g_Kh, g_Kl);
}

__global__ __launch_bounds__(256, 1)
void out_gemm_kernel(const float* __restrict__ bo, float* __restrict__ out)
{
    gemm_core(g_AOh, g_Wohi, g_Wolo, bo, 1.0f, out, nullptr, nullptr);
}

// ---------------------------------------------------------------------------
// HMMA flash attention, fp16: QK^T 3-pass, PV 2-pass.
// grid (32 = B*NH, 16 = SEQ/128), 256 threads (8 warps), 128 q-rows per CTA.
// ---------------------------------------------------------------------------
#define SLDT 72                        // 144 B row
#define ATILE (64 * SLDT * 2)          // 9216 B per array
#define AST   (4 * ATILE)              // 36864 B per stage

__global__ __launch_bounds__(256, 1)
void attn_mma_kernel()
{
    extern __shared__ char dsm[];
    __half* pool = (__half*)dsm;

    const int tid = threadIdx.x;
    const int wid = tid >> 5;
    const int lid = tid & 31;
    const int b   = blockIdx.x >> 4;
    const int h   = blockIdx.x & 15;
    const int q0  = blockIdx.y * 128;

    const int lr     = lid & 7;
    const int half2_ = (lid >> 3) & 1;
    const int kh     = (lid >> 4) & 1;

    const uint32_t smem_base = smem_to_u32(dsm);

    // ---- stage Q tile (128 x 64, hi/lo) through stage-0 area, extract frags ----
#pragma unroll
    for (int i = 0; i < 8; i++) {
        int e   = tid + i * 256;
        int arr = e >> 10;
        int rem = e & 1023;
        int row = rem >> 3;
        int c   = rem & 7;
        const __half* src = (arr ? g_Ql : g_Qh)
            + (size_t)(b * SEQ + q0 + row) * D_MODEL + h * HDIM + c * 8;
        *(uint4*)(pool + arr * 128 * SLDT + row * SLDT + c * 8) = *(const uint4*)src;
    }
    __syncthreads();

    uint32_t qh[4][4], ql[4][4];
    {
        const int wr = wid * 16;
        const uint32_t uQh = smem_base;
        const uint32_t uQl = smem_base + 128 * SLDT * 2;
#pragma unroll
        for (int kc = 0; kc < 4; kc++) {
            int row = wr + lr + 8 * half2_;
            int col = kc * 16 + kh * 8;
            ldsm_x4(qh[kc][0], qh[kc][1], qh[kc][2], qh[kc][3],
                    uQh + (uint32_t)(row * SLDT + col) * 2);
            ldsm_x4(ql[kc][0], ql[kc][1], ql[kc][2], ql[kc][3],
                    uQl + (uint32_t)(row * SLDT + col) * 2);
        }
    }
    __syncthreads();

    float oacc[8][4];
#pragma unroll
    for (int nt = 0; nt < 8; nt++)
#pragma unroll
        for (int c = 0; c < 4; c++) oacc[nt][c] = 0.0f;
    float mx0 = -1e30f, mx1 = -1e30f, l0 = 0.0f, l1 = 0.0f;

    auto load_stage = [&](int kt, int s) {
        const int kb = kt * 64;
        uint32_t sb = smem_base + s * AST;
#pragma unroll
        for (int i = 0; i < 8; i++) {
            int arr = i >> 1;
            int rem = ((i & 1) << 8) + tid;
            int row = rem >> 3;
            int c   = rem & 7;
            const __half* g =
                (arr == 0 ? g_Kh : arr == 1 ? g_Kl : arr == 2 ? g_Hhi : g_Hlo)
                + (size_t)(b * SEQ + kb + row) * D_MODEL + h * HDIM + c * 8;
            cp16(sb + arr * ATILE + row * (SLDT * 2) + c * 16, g);
        }
        CP_COMMIT();
    };

    load_stage(0, 0);

    for (int kt = 0; kt < SEQ / 64; kt++) {
        const int s = kt & 1;
        CP_WAIT0();
        __syncthreads();
        if (kt + 1 < SEQ / 64) load_stage(kt + 1, s ^ 1);

        const uint32_t sb  = smem_base + s * AST;
        const uint32_t uKh = sb;
        const uint32_t uKl = sb + ATILE;
        const uint32_t uVh = sb + 2 * ATILE;
        const uint32_t uVl = sb + 3 * ATILE;

        // ---- S = Q K^T (3-pass fp16) ----
        float S[8][4];
#pragma unroll
        for (int nt = 0; nt < 8; nt++)
#pragma unroll
            for (int c = 0; c < 4; c++) S[nt][c] = 0.0f;

#pragma unroll
        for (int kc = 0; kc < 4; kc++) {
            uint32_t kbh[8][2], kbl[8][2];
#pragma unroll
            for (int ng = 0; ng < 4; ng++) {
                int row = ng * 16 + lr + 8 * half2_;
                int col = kc * 16 + kh * 8;
                uint32_t r0, r1, r2, r3;
                ldsm_x4(r0, r1, r2, r3, uKh + (uint32_t)(row * SLDT + col) * 2);
                kbh[ng * 2 + 0][0] = r0; kbh[ng * 2 + 0][1] = r2;
                kbh[ng * 2 + 1][0] = r1; kbh[ng * 2 + 1][1] = r3;
                ldsm_x4(r0, r1, r2, r3, uKl + (uint32_t)(row * SLDT + col) * 2);
                kbl[ng * 2 + 0][0] = r0; kbl[ng * 2 + 0][1] = r2;
                kbl[ng * 2 + 1][0] = r1; kbl[ng * 2 + 1][1] = r3;
            }
#pragma unroll
            for (int nt = 0; nt < 8; nt++)
                mma16816(S[nt], qh[kc], kbh[nt]);
#pragma unroll
            for (int nt = 0; nt < 8; nt++)
                mma16816(S[nt], qh[kc], kbl[nt]);
#pragma unroll
            for (int nt = 0; nt < 8; nt++)
                mma16816(S[nt], ql[kc], kbh[nt]);
        }

        // ---- online softmax ----
        float tm0 = -1e30f, tm1 = -1e30f;
#pragma unroll
        for (int nt = 0; nt < 8; nt++) {
            tm0 = fmaxf(tm0, fmaxf(S[nt][0], S[nt][1]));
            tm1 = fmaxf(tm1, fmaxf(S[nt][2], S[nt][3]));
        }
        tm0 = fmaxf(tm0, __shfl_xor_sync(0xffffffffu, tm0, 1));
        tm0 = fmaxf(tm0, __shfl_xor_sync(0xffffffffu, tm0, 2));
        tm1 = fmaxf(tm1, __shfl_xor_sync(0xffffffffu, tm1, 1));
        tm1 = fmaxf(tm1, __shfl_xor_sync(0xffffffffu, tm1, 2));
        float mn0 = fmaxf(mx0, tm0), mn1 = fmaxf(mx1, tm1);
        float a0 = ex2f(mx0 - mn0), a1 = ex2f(mx1 - mn1);

        // ---- P (single fp16 fragments) ----
        uint32_t pa[4][4];
        float rs0 = 0.0f, rs1 = 0.0f;
#pragma unroll
        for (int j = 0; j < 4; j++) {
#pragma unroll
            for (int sg = 0; sg < 2; sg++) {
                int t2 = j * 2 + sg;
                float p0 = ex2f(S[t2][0] - mn0);
                float p1 = ex2f(S[t2][1] - mn0);
                float p2 = ex2f(S[t2][2] - mn1);
                float p3 = ex2f(S[t2][3] - mn1);
                rs0 += p0 + p1;
                rs1 += p2 + p3;
                pa[j][sg * 2 + 0] = packh2(p0, p1);
                pa[j][sg * 2 + 1] = packh2(p2, p3);
            }
        }
        rs0 += __shfl_xor_sync(0xffffffffu, rs0, 1);
        rs0 += __shfl_xor_sync(0xffffffffu, rs0, 2);
        rs1 += __shfl_xor_sync(0xffffffffu, rs1, 1);
        rs1 += __shfl_xor_sync(0xffffffffu, rs1, 2);
        l0 = l0 * a0 + rs0;
        l1 = l1 * a1 + rs1;
        mx0 = mn0; mx1 = mn1;
#pragma unroll
        for (int nt = 0; nt < 8; nt++) {
            oacc[nt][0] *= a0; oacc[nt][1] *= a0;
            oacc[nt][2] *= a1; oacc[nt][3] *= a1;
        }

        // ---- O += P V (2-pass) ----
#pragma unroll
        for (int kc = 0; kc < 4; kc++) {
            uint32_t vbh[8][2], vbl[8][2];
#pragma unroll
            for (int dg = 0; dg < 4; dg++) {
                int rowk = kc * 16 + lr + 8 * half2_;
                int dimc = dg * 16 + kh * 8;
                uint32_t r0, r1, r2, r3;
                ldsm_x4_t(r0, r1, r2, r3, uVh + (uint32_t)(rowk * SLDT + dimc) * 2);
                vbh[dg * 2 + 0][0] = r0; vbh[dg * 2 + 0][1] = r1;
                vbh[dg * 2 + 1][0] = r2; vbh[dg * 2 + 1][1] = r3;
                ldsm_x4_t(r0, r1, r2, r3, uVl + (uint32_t)(rowk * SLDT + dimc) * 2);
                vbl[dg * 2 + 0][0] = r0; vbl[dg * 2 + 0][1] = r1;
                vbl[dg * 2 + 1][0] = r2; vbl[dg * 2 + 1][1] = r3;
            }
#pragma unroll
            for (int nt = 0; nt < 8; nt++)
                mma16816(oacc[nt], pa[kc], vbh[nt]);
#pragma unroll
            for (int nt = 0; nt < 8; nt++)
                mma16816(oacc[nt], pa[kc], vbl[nt]);
        }
    }

    // ---- epilogue: normalize, store fp16 hi only (out_gemm is 2-pass) ----
    const float inv0 = 1.0f / l0;
    const float inv1 = 1.0f / l1;
    const int gr  = b * SEQ + q0 + wid * 16 + (lid >> 2);
    const int col = h * HDIM + (lid & 3) * 2;
#pragma unroll
    for (int nt = 0; nt < 8; nt++) {
        int gc = col + nt * 8;
        float v0 = oacc[nt][0] * inv0, v1 = oacc[nt][1] * inv0;
        float v2 = oacc[nt][2] * inv1, v3 = oacc[nt][3] * inv1;
        *(uint32_t*)&g_AOh[(size_t)gr * D_MODEL + gc]       = packh2(v0, v1);
        *(uint32_t*)&g_AOh[(size_t)(gr + 8) * D_MODEL + gc] = packh2(v2, v3);
    }
}

// ---------------------------------------------------------------------------
extern "C" void kernel_launch(void* const* d_in, const int* in_sizes, int n_in,
                              void* d_out, int out_size)
{
    (void)in_sizes; (void)n_in; (void)out_size;
    const float* H  = (const float*)d_in[0];
    const float* Wq = (const float*)d_in[1];
    const float* bq = (const float*)d_in[2];
    const float* Wk = (const float*)d_in[3];
    const float* bk = (const float*)d_in[4];
    const float* Wo = (const float*)d_in[5];
    const float* bo = (const float*)d_in[6];
    float* out = (float*)d_out;

    void *p_Hhi, *p_Hlo;
    void *p_Wqhi, *p_Wqlo, *p_Wkhi, *p_Wklo, *p_Wohi, *p_Wolo;
    cudaGetSymbolAddress(&p_Hhi,  g_Hhi);  cudaGetSymbolAddress(&p_Hlo,  g_Hlo);
    cudaGetSymbolAddress(&p_Wqhi, g_Wqhi); cudaGetSymbolAddress(&p_Wqlo, g_Wqlo);
    cudaGetSymbolAddress(&p_Wkhi, g_Wkhi); cudaGetSymbolAddress(&p_Wklo, g_Wklo);
    cudaGetSymbolAddress(&p_Wohi, g_Wohi); cudaGetSymbolAddress(&p_Wolo, g_Wolo);

    cudaFuncSetAttribute(qk_gemm_kernel,
                         cudaFuncAttributeMaxDynamicSharedMemorySize, 2 * GST);
    cudaFuncSetAttribute(out_gemm_kernel,
                         cudaFuncAttributeMaxDynamicSharedMemorySize, 2 * GST);
    cudaFuncSetAttribute(attn_mma_kernel,
                         cudaFuncAttributeMaxDynamicSharedMemorySize, 2 * AST);

    const int nH4 = NROWS * D_MODEL / 4;      // 1,048,576
    const int nW4 = D_MODEL * D_MODEL / 4;    // 262,144
    const int nTot = nH4 + 3 * nW4;           // 1,835,008

    split4_kernel<<<(nTot + 255) / 256, 256>>>(
        (const float4*)H,  (uint2*)p_Hhi,  (uint2*)p_Hlo,  nH4,
        (const float4*)Wq, (uint2*)p_Wqhi, (uint2*)p_Wqlo, nW4,
        (const float4*)Wk, (uint2*)p_Wkhi, (uint2*)p_Wklo, nW4,
        (const float4*)Wo, (uint2*)p_Wohi, (uint2*)p_Wolo, nW4);

    dim3 ggrid(D_MODEL / BN, NROWS / BM, 2);   // (8, 32, 2)
    qk_gemm_kernel<<<ggrid, 256, 2 * GST>>>(bq, bk);

    dim3 agrid(BATCH * NHEADS, SEQ / 128);     // (32, 16)
    attn_mma_kernel<<<agrid, 256, 2 * AST>>>();

    dim3 ogrid(D_MODEL / BN, NROWS / BM, 1);   // (8, 32)
    out_gemm_kernel<<<ogrid, 256, 2 * GST>>>(bo, out);
}

// round 9
// speedup vs baseline: 1.3054x; 1.0904x over previous
#include <cuda_runtime.h>
#include <cuda_fp16.h>
#include <cstdint>

#define D_MODEL 1024
#define NHEADS  16
#define HDIM    64
#define BATCH   2
#define SEQ     2048
#define NROWS   (BATCH * SEQ)     // 4096
#define KDIM    D_MODEL

// softmax scale folded into Q projection: 1/sqrt(64) * log2(e)
#define QK_SCALE 0.1803368801111244f

// ---------------------------------------------------------------------------
// Scratch (device globals)
// ---------------------------------------------------------------------------
__device__ __half g_Hhi [NROWS * D_MODEL];
__device__ __half g_Hlo [NROWS * D_MODEL];   // V-lo in attention
__device__ __half g_Qh  [NROWS * D_MODEL];
__device__ __half g_Kh  [NROWS * D_MODEL];
__device__ __half g_Kl  [NROWS * D_MODEL];
__device__ __half g_AOh [NROWS * D_MODEL];
__device__ __half g_Wqhi[D_MODEL * D_MODEL];
__device__ __half g_Wqlo[D_MODEL * D_MODEL];
__device__ __half g_Wkhi[D_MODEL * D_MODEL];
__device__ __half g_Wklo[D_MODEL * D_MODEL];
__device__ __half g_Wohi[D_MODEL * D_MODEL];
__device__ __half g_Wolo[D_MODEL * D_MODEL];  // written by split, unused (1-pass out)

// ---------------------------------------------------------------------------
// helpers
// ---------------------------------------------------------------------------
__device__ __forceinline__ uint32_t smem_to_u32(const void* p) {
    uint32_t a;
    asm("{ .reg .u64 t; cvta.to.shared.u64 t, %1; cvt.u32.u64 %0, t; }"
        : "=r"(a) : "l"(p));
    return a;
}
__device__ __forceinline__ void ldsm_x4(uint32_t& r0, uint32_t& r1,
                                        uint32_t& r2, uint32_t& r3, uint32_t addr) {
    asm volatile("ldmatrix.sync.aligned.m8n8.x4.shared.b16 {%0,%1,%2,%3}, [%4];"
                 : "=r"(r0), "=r"(r1), "=r"(r2), "=r"(r3) : "r"(addr));
}
__device__ __forceinline__ void ldsm_x4_t(uint32_t& r0, uint32_t& r1,
                                          uint32_t& r2, uint32_t& r3, uint32_t addr) {
    asm volatile("ldmatrix.sync.aligned.m8n8.x4.trans.shared.b16 {%0,%1,%2,%3}, [%4];"
                 : "=r"(r0), "=r"(r1), "=r"(r2), "=r"(r3) : "r"(addr));
}
__device__ __forceinline__ void mma16816(float* c, const uint32_t* a,
                                         const uint32_t* b) {
    asm volatile(
        "mma.sync.aligned.m16n8k16.row.col.f32.f16.f16.f32 "
        "{%0,%1,%2,%3}, {%4,%5,%6,%7}, {%8,%9}, {%0,%1,%2,%3};"
        : "+f"(c[0]), "+f"(c[1]), "+f"(c[2]), "+f"(c[3])
        : "r"(a[0]), "r"(a[1]), "r"(a[2]), "r"(a[3]), "r"(b[0]), "r"(b[1]));
}
__device__ __forceinline__ float ex2f(float x) {
    float r;
    asm("ex2.approx.ftz.f32 %0, %1;" : "=f"(r) : "f"(x));
    return r;
}
__device__ __forceinline__ uint32_t packh2(float a, float b) {
    __half2 t = __floats2half2_rn(a, b);
    return *(uint32_t*)&t;
}
__device__ __forceinline__ void cp16(uint32_t smem, const void* g) {
    asm volatile("cp.async.cg.shared.global [%0], [%1], 16;"
                 :: "r"(smem), "l"(g) : "memory");
}
#define CP_COMMIT() asm volatile("cp.async.commit_group;" ::: "memory")
#define CP_WAIT0()  asm volatile("cp.async.wait_group 0;" ::: "memory")
#define CP_WAIT1()  asm volatile("cp.async.wait_group 1;" ::: "memory")

// ---------------------------------------------------------------------------
// fp32 -> (fp16 hi, fp16 lo) split, 4 tensors in one launch
// ---------------------------------------------------------------------------
__device__ __forceinline__ void split4_do(const float4* src, uint2* hi, uint2* lo, int i)
{
    float4 v = src[i];
    __half h0 = __float2half_rn(v.x), h1 = __float2half_rn(v.y);
    __half h2 = __float2half_rn(v.z), h3 = __float2half_rn(v.w);
    float r0 = v.x - __half2float(h0), r1 = v.y - __half2float(h1);
    float r2 = v.z - __half2float(h2), r3 = v.w - __half2float(h3);
    hi[i] = make_uint2(
        (uint32_t)__half_as_ushort(h0) | ((uint32_t)__half_as_ushort(h1) << 16),
        (uint32_t)__half_as_ushort(h2) | ((uint32_t)__half_as_ushort(h3) << 16));
    lo[i] = make_uint2(packh2(r0, r1), packh2(r2, r3));
}

__global__ __launch_bounds__(256)
void split4_kernel(const float4* s0, uint2* h0, uint2* l0, int n0,
                   const float4* s1, uint2* h1, uint2* l1, int n1,
                   const float4* s2, uint2* h2, uint2* l2, int n2,
                   const float4* s3, uint2* h3, uint2* l3, int n3)
{
    int i = blockIdx.x * blockDim.x + threadIdx.x;
    if (i < n0) { split4_do(s0, h0, l0, i); return; }
    i -= n0;
    if (i < n1) { split4_do(s1, h1, l1, i); return; }
    i -= n1;
    if (i < n2) { split4_do(s2, h2, l2, i); return; }
    i -= n2;
    if (i < n3) { split4_do(s3, h3, l3, i); }
}

// ---------------------------------------------------------------------------
// HMMA GEMM, PASSES-template: C = Ahi*Whi (+ Ahi*Wlo if PASSES==2) + bias.
// CTA 128x128, BK=64, 256 threads (8 warps), 3-stage cp.async pipeline.
// ---------------------------------------------------------------------------
#define BM 128
#define BN 128
#define BKK 64
#define LDT 72                     // 144 B row (9 x 16B) -> LDSM conflict-free
#define GTILE (BM * LDT * 2)       // 18432 B per array
#define GNIT  (KDIM / BKK)         // 16

template <int PASSES>
__device__ __forceinline__ void gemm_core(
    const __half* __restrict__ Ahi,
    const __half* __restrict__ Whi, const __half* __restrict__ Wlo,
    const float* __restrict__ bias, float scale,
    float* __restrict__ Cf, __half* __restrict__ Ch, __half* __restrict__ Cl)
{
    constexpr int NARR = 1 + PASSES;          // arrays per stage
    constexpr int GST  = NARR * GTILE;        // bytes per stage

    extern __shared__ char dsm[];
    __shared__ float s_bias[BN];

    const int tid = threadIdx.x;
    const int wid = tid >> 5;
    const int lid = tid & 31;
    const int wm  = wid & 1;
    const int wn  = wid >> 1;
    const int m0  = blockIdx.y * BM;
    const int n0  = blockIdx.x * BN;

    if (tid < BN) s_bias[tid] = bias[n0 + tid];

    const int lr     = lid & 7;
    const int half2_ = (lid >> 3) & 1;
    const int kh     = (lid >> 4) & 1;
    const int mbase  = wm * 64;
    const int nbase  = wn * 32;

    const uint32_t smem_base = smem_to_u32(dsm);

    float acc[4][4][4];
#pragma unroll
    for (int i = 0; i < 4; i++)
#pragma unroll
        for (int j = 0; j < 4; j++)
#pragma unroll
            for (int c = 0; c < 4; c++) acc[i][j][c] = 0.0f;

    auto load_stage = [&](int k0, int s) {
        uint32_t sb = smem_base + s * GST;
#pragma unroll
        for (int it = 0; it < 4 * NARR; it++) {
            int e    = tid + it * 256;
            int arr  = e >> 10;             // 0 Ahi, 1 Whi, 2 Wlo
            int rem  = e & 1023;
            int row  = rem >> 3;
            int c    = rem & 7;
            const __half* g;
            if (arr == 0)      g = Ahi + (size_t)(m0 + row) * KDIM + k0 + c * 8;
            else if (arr == 1) g = Whi + (size_t)(n0 + row) * KDIM + k0 + c * 8;
            else               g = Wlo + (size_t)(n0 + row) * KDIM + k0 + c * 8;
            cp16(sb + arr * GTILE + row * (LDT * 2) + c * 16, g);
        }
        CP_COMMIT();
    };

    load_stage(0, 0);
    load_stage(BKK, 1);

    for (int i = 0; i < GNIT; i++) {
        if (i + 1 < GNIT) { CP_WAIT1(); } else { CP_WAIT0(); }
        __syncthreads();
        if (i + 2 < GNIT) load_stage((i + 2) * BKK, (i + 2) % 3);

        const uint32_t sb   = smem_base + (i % 3) * GST;
        const uint32_t uAhi = sb;
        const uint32_t uWhi = sb + GTILE;
        const uint32_t uWlo = sb + 2 * GTILE;

#pragma unroll
        for (int ks = 0; ks < 4; ks++) {
            const int kcol = ks * 16 + kh * 8;

            uint32_t ahi[4][4];
#pragma unroll
            for (int mt = 0; mt < 4; mt++) {
                int row = mbase + mt * 16 + lr + 8 * half2_;
                ldsm_x4(ahi[mt][0], ahi[mt][1], ahi[mt][2], ahi[mt][3],
                        uAhi + (uint32_t)(row * LDT + kcol) * 2);
            }
            uint32_t bhi[4][2], blo[4][2];
#pragma unroll
            for (int ntp = 0; ntp < 2; ntp++) {
                int row = nbase + ntp * 16 + lr + 8 * half2_;
                uint32_t r0, r1, r2, r3;
                ldsm_x4(r0, r1, r2, r3, uWhi + (uint32_t)(row * LDT + kcol) * 2);
                bhi[ntp * 2 + 0][0] = r0; bhi[ntp * 2 + 0][1] = r2;
                bhi[ntp * 2 + 1][0] = r1; bhi[ntp * 2 + 1][1] = r3;
                if (PASSES == 2) {
                    ldsm_x4(r0, r1, r2, r3, uWlo + (uint32_t)(row * LDT + kcol) * 2);
                    blo[ntp * 2 + 0][0] = r0; blo[ntp * 2 + 0][1] = r2;
                    blo[ntp * 2 + 1][0] = r1; blo[ntp * 2 + 1][1] = r3;
                }
            }
#pragma unroll
            for (int mt = 0; mt < 4; mt++)
#pragma unroll
                for (int nt = 0; nt < 4; nt++)
                    mma16816(acc[mt][nt], ahi[mt], bhi[nt]);
            if (PASSES == 2) {
#pragma unroll
                for (int mt = 0; mt < 4; mt++)
#pragma unroll
                    for (int nt = 0; nt < 4; nt++)
                        mma16816(acc[mt][nt], ahi[mt], blo[nt]);
            }
        }
    }

    const int erow = lid >> 2;
    const int ecol = (lid & 3) * 2;
#pragma unroll
    for (int mt = 0; mt < 4; mt++) {
#pragma unroll
        for (int nt = 0; nt < 4; nt++) {
            int gm = m0 + mbase + mt * 16 + erow;
            int nc = nbase + nt * 8 + ecol;
            int gn = n0 + nc;
            float v0 = (acc[mt][nt][0] + s_bias[nc])     * scale;
            float v1 = (acc[mt][nt][1] + s_bias[nc + 1]) * scale;
            float v2 = (acc[mt][nt][2] + s_bias[nc])     * scale;
            float v3 = (acc[mt][nt][3] + s_bias[nc + 1]) * scale;
            if (Ch) {
                __half h0 = __float2half_rn(v0), h1 = __float2half_rn(v1);
                __half h2 = __float2half_rn(v2), h3 = __float2half_rn(v3);
                *(uint32_t*)&Ch[(size_t)gm * D_MODEL + gn] =
                    (uint32_t)__half_as_ushort(h0) | ((uint32_t)__half_as_ushort(h1) << 16);
                *(uint32_t*)&Ch[(size_t)(gm + 8) * D_MODEL + gn] =
                    (uint32_t)__half_as_ushort(h2) | ((uint32_t)__half_as_ushort(h3) << 16);
                if (Cl) {
                    *(uint32_t*)&Cl[(size_t)gm * D_MODEL + gn] =
                        packh2(v0 - __half2float(h0), v1 - __half2float(h1));
                    *(uint32_t*)&Cl[(size_t)(gm + 8) * D_MODEL + gn] =
                        packh2(v2 - __half2float(h2), v3 - __half2float(h3));
                }
            } else {
                *(float2*)&Cf[(size_t)gm * D_MODEL + gn]       = make_float2(v0, v1);
                *(float2*)&Cf[(size_t)(gm + 8) * D_MODEL + gn] = make_float2(v2, v3);
            }
        }
    }
}

__global__ __launch_bounds__(256, 1)
void qk_gemm_kernel(const float* __restrict__ bq, const float* __restrict__ bk)
{
    if (blockIdx.z == 0)   // Q: hi only (Q-lo unused by 2-pass QK^T)
        gemm_core<2>(g_Hhi, g_Wqhi, g_Wqlo, bq, QK_SCALE, nullptr, g_Qh, nullptr);
    else                   // K: hi + lo
        gemm_core<2>(g_Hhi, g_Wkhi, g_Wklo, bk, 1.0f, nullptr, g_Kh, g_Kl);
}

__global__ __launch_bounds__(256, 1)
void out_gemm_kernel(const float* __restrict__ bo, float* __restrict__ out)
{
    gemm_core<1>(g_AOh, g_Wohi, nullptr, bo, 1.0f, out, nullptr, nullptr);
}

// ---------------------------------------------------------------------------
// HMMA flash attention: QK^T 2-pass (QhKh + QhKl), PV 2-pass. 3-stage pipeline.
// grid (32 = B*NH, 16 = SEQ/128), 256 threads (8 warps), 128 q-rows per CTA.
// ---------------------------------------------------------------------------
#define SLDT 72                        // 144 B row
#define ATILE (64 * SLDT * 2)          // 9216 B per array
#define AST   (4 * ATILE)              // 36864 B per stage
#define KTILES (SEQ / 64)              // 32

__global__ __launch_bounds__(256, 1)
void attn_mma_kernel()
{
    extern __shared__ char dsm[];
    __half* pool = (__half*)dsm;

    const int tid = threadIdx.x;
    const int wid = tid >> 5;
    const int lid = tid & 31;
    const int b   = blockIdx.x >> 4;
    const int h   = blockIdx.x & 15;
    const int q0  = blockIdx.y * 128;

    const int lr     = lid & 7;
    const int half2_ = (lid >> 3) & 1;
    const int kh     = (lid >> 4) & 1;

    const uint32_t smem_base = smem_to_u32(dsm);

    // ---- stage Q-hi tile (128 x 64) through stage-0 area, extract frags ----
#pragma unroll
    for (int i = 0; i < 4; i++) {
        int e   = tid + i * 256;            // 0..1023
        int row = e >> 3;
        int c   = e & 7;
        const __half* src = g_Qh
            + (size_t)(b * SEQ + q0 + row) * D_MODEL + h * HDIM + c * 8;
        *(uint4*)(pool + row * SLDT + c * 8) = *(const uint4*)src;
    }
    __syncthreads();

    uint32_t qh[4][4];
    {
        const int wr = wid * 16;
#pragma unroll
        for (int kc = 0; kc < 4; kc++) {
            int row = wr + lr + 8 * half2_;
            int col = kc * 16 + kh * 8;
            ldsm_x4(qh[kc][0], qh[kc][1], qh[kc][2], qh[kc][3],
                    smem_base + (uint32_t)(row * SLDT + col) * 2);
        }
    }
    __syncthreads();

    float oacc[8][4];
#pragma unroll
    for (int nt = 0; nt < 8; nt++)
#pragma unroll
        for (int c = 0; c < 4; c++) oacc[nt][c] = 0.0f;
    float mx0 = -1e30f, mx1 = -1e30f, l0 = 0.0f, l1 = 0.0f;

    auto load_stage = [&](int kt, int s) {
        const int kb = kt * 64;
        uint32_t sb = smem_base + s * AST;
#pragma unroll
        for (int i = 0; i < 8; i++) {
            int arr = i >> 1;                       // 0 Kh, 1 Kl, 2 Vh, 3 Vl
            int rem = ((i & 1) << 8) + tid;
            int row = rem >> 3;
            int c   = rem & 7;
            const __half* g =
                (arr == 0 ? g_Kh : arr == 1 ? g_Kl : arr == 2 ? g_Hhi : g_Hlo)
                + (size_t)(b * SEQ + kb + row) * D_MODEL + h * HDIM + c * 8;
            cp16(sb + arr * ATILE + row * (SLDT * 2) + c * 16, g);
        }
        CP_COMMIT();
    };

    load_stage(0, 0);
    load_stage(1, 1);

    for (int kt = 0; kt < KTILES; kt++) {
        if (kt + 1 < KTILES) { CP_WAIT1(); } else { CP_WAIT0(); }
        __syncthreads();
        if (kt + 2 < KTILES) load_stage(kt + 2, (kt + 2) % 3);

        const uint32_t sb  = smem_base + (kt % 3) * AST;
        const uint32_t uKh = sb;
        const uint32_t uKl = sb + ATILE;
        const uint32_t uVh = sb + 2 * ATILE;
        const uint32_t uVl = sb + 3 * ATILE;

        // ---- S = Q K^T (2-pass: QhKh + QhKl) ----
        float S[8][4];
#pragma unroll
        for (int nt = 0; nt < 8; nt++)
#pragma unroll
            for (int c = 0; c < 4; c++) S[nt][c] = 0.0f;

#pragma unroll
        for (int kc = 0; kc < 4; kc++) {
            uint32_t kbh[8][2], kbl[8][2];
#pragma unroll
            for (int ng = 0; ng < 4; ng++) {
                int row = ng * 16 + lr + 8 * half2_;
                int col = kc * 16 + kh * 8;
                uint32_t r0, r1, r2, r3;
                ldsm_x4(r0, r1, r2, r3, uKh + (uint32_t)(row * SLDT + col) * 2);
                kbh[ng * 2 + 0][0] = r0; kbh[ng * 2 + 0][1] = r2;
                kbh[ng * 2 + 1][0] = r1; kbh[ng * 2 + 1][1] = r3;
                ldsm_x4(r0, r1, r2, r3, uKl + (uint32_t)(row * SLDT + col) * 2);
                kbl[ng * 2 + 0][0] = r0; kbl[ng * 2 + 0][1] = r2;
                kbl[ng * 2 + 1][0] = r1; kbl[ng * 2 + 1][1] = r3;
            }
#pragma unroll
            for (int nt = 0; nt < 8; nt++)
                mma16816(S[nt], qh[kc], kbh[nt]);
#pragma unroll
            for (int nt = 0; nt < 8; nt++)
                mma16816(S[nt], qh[kc], kbl[nt]);
        }

        // ---- online softmax ----
        float tm0 = -1e30f, tm1 = -1e30f;
#pragma unroll
        for (int nt = 0; nt < 8; nt++) {
            tm0 = fmaxf(tm0, fmaxf(S[nt][0], S[nt][1]));
            tm1 = fmaxf(tm1, fmaxf(S[nt][2], S[nt][3]));
        }
        tm0 = fmaxf(tm0, __shfl_xor_sync(0xffffffffu, tm0, 1));
        tm0 = fmaxf(tm0, __shfl_xor_sync(0xffffffffu, tm0, 2));
        tm1 = fmaxf(tm1, __shfl_xor_sync(0xffffffffu, tm1, 1));
        tm1 = fmaxf(tm1, __shfl_xor_sync(0xffffffffu, tm1, 2));
        float mn0 = fmaxf(mx0, tm0), mn1 = fmaxf(mx1, tm1);
        float a0 = ex2f(mx0 - mn0), a1 = ex2f(mx1 - mn1);

        uint32_t pa[4][4];
        float rs0 = 0.0f, rs1 = 0.0f;
#pragma unroll
        for (int j = 0; j < 4; j++) {
#pragma unroll
            for (int sg = 0; sg < 2; sg++) {
                int t2 = j * 2 + sg;
                float p0 = ex2f(S[t2][0] - mn0);
                float p1 = ex2f(S[t2][1] - mn0);
                float p2 = ex2f(S[t2][2] - mn1);
                float p3 = ex2f(S[t2][3] - mn1);
                rs0 += p0 + p1;
                rs1 += p2 + p3;
                pa[j][sg * 2 + 0] = packh2(p0, p1);
                pa[j][sg * 2 + 1] = packh2(p2, p3);
            }
        }
        rs0 += __shfl_xor_sync(0xffffffffu, rs0, 1);
        rs0 += __shfl_xor_sync(0xffffffffu, rs0, 2);
        rs1 += __shfl_xor_sync(0xffffffffu, rs1, 1);
        rs1 += __shfl_xor_sync(0xffffffffu, rs1, 2);
        l0 = l0 * a0 + rs0;
        l1 = l1 * a1 + rs1;
        mx0 = mn0; mx1 = mn1;
#pragma unroll
        for (int nt = 0; nt < 8; nt++) {
            oacc[nt][0] *= a0; oacc[nt][1] *= a0;
            oacc[nt][2] *= a1; oacc[nt][3] *= a1;
        }

        // ---- O += P V (2-pass) ----
#pragma unroll
        for (int kc = 0; kc < 4; kc++) {
            uint32_t vbh[8][2], vbl[8][2];
#pragma unroll
            for (int dg = 0; dg < 4; dg++) {
                int rowk = kc * 16 + lr + 8 * half2_;
                int dimc = dg * 16 + kh * 8;
                uint32_t r0, r1, r2, r3;
                ldsm_x4_t(r0, r1, r2, r3, uVh + (uint32_t)(rowk * SLDT + dimc) * 2);
                vbh[dg * 2 + 0][0] = r0; vbh[dg * 2 + 0][1] = r1;
                vbh[dg * 2 + 1][0] = r2; vbh[dg * 2 + 1][1] = r3;
                ldsm_x4_t(r0, r1, r2, r3, uVl + (uint32_t)(rowk * SLDT + dimc) * 2);
                vbl[dg * 2 + 0][0] = r0; vbl[dg * 2 + 0][1] = r1;
                vbl[dg * 2 + 1][0] = r2; vbl[dg * 2 + 1][1] = r3;
            }
#pragma unroll
            for (int nt = 0; nt < 8; nt++)
                mma16816(oacc[nt], pa[kc], vbh[nt]);
#pragma unroll
            for (int nt = 0; nt < 8; nt++)
                mma16816(oacc[nt], pa[kc], vbl[nt]);
        }
    }

    // ---- epilogue ----
    const float inv0 = 1.0f / l0;
    const float inv1 = 1.0f / l1;
    const int gr  = b * SEQ + q0 + wid * 16 + (lid >> 2);
    const int col = h * HDIM + (lid & 3) * 2;
#pragma unroll
    for (int nt = 0; nt < 8; nt++) {
        int gc = col + nt * 8;
        float v0 = oacc[nt][0] * inv0, v1 = oacc[nt][1] * inv0;
        float v2 = oacc[nt][2] * inv1, v3 = oacc[nt][3] * inv1;
        *(uint32_t*)&g_AOh[(size_t)gr * D_MODEL + gc]       = packh2(v0, v1);
        *(uint32_t*)&g_AOh[(size_t)(gr + 8) * D_MODEL + gc] = packh2(v2, v3);
    }
}

// ---------------------------------------------------------------------------
extern "C" void kernel_launch(void* const* d_in, const int* in_sizes, int n_in,
                              void* d_out, int out_size)
{
    (void)in_sizes; (void)n_in; (void)out_size;
    const float* H  = (const float*)d_in[0];
    const float* Wq = (const float*)d_in[1];
    const float* bq = (const float*)d_in[2];
    const float* Wk = (const float*)d_in[3];
    const float* bk = (const float*)d_in[4];
    const float* Wo = (const float*)d_in[5];
    const float* bo = (const float*)d_in[6];
    float* out = (float*)d_out;

    void *p_Hhi, *p_Hlo;
    void *p_Wqhi, *p_Wqlo, *p_Wkhi, *p_Wklo, *p_Wohi, *p_Wolo;
    cudaGetSymbolAddress(&p_Hhi,  g_Hhi);  cudaGetSymbolAddress(&p_Hlo,  g_Hlo);
    cudaGetSymbolAddress(&p_Wqhi, g_Wqhi); cudaGetSymbolAddress(&p_Wqlo, g_Wqlo);
    cudaGetSymbolAddress(&p_Wkhi, g_Wkhi); cudaGetSymbolAddress(&p_Wklo, g_Wklo);
    cudaGetSymbolAddress(&p_Wohi, g_Wohi); cudaGetSymbolAddress(&p_Wolo, g_Wolo);

    const int GSMEM2 = 3 * (3 * GTILE);   // 165,888 B (2-pass gemm, 3 stages)
    const int GSMEM1 = 3 * (2 * GTILE);   // 110,592 B (1-pass gemm, 3 stages)
    const int ASMEM  = 3 * AST;           // 110,592 B

    cudaFuncSetAttribute(qk_gemm_kernel,
                         cudaFuncAttributeMaxDynamicSharedMemorySize, GSMEM2);
    cudaFuncSetAttribute(out_gemm_kernel,
                         cudaFuncAttributeMaxDynamicSharedMemorySize, GSMEM1);
    cudaFuncSetAttribute(attn_mma_kernel,
                         cudaFuncAttributeMaxDynamicSharedMemorySize, ASMEM);

    const int nH4 = NROWS * D_MODEL / 4;      // 1,048,576
    const int nW4 = D_MODEL * D_MODEL / 4;    // 262,144
    const int nTot = nH4 + 3 * nW4;           // 1,835,008

    split4_kernel<<<(nTot + 255) / 256, 256>>>(
        (const float4*)H,  (uint2*)p_Hhi,  (uint2*)p_Hlo,  nH4,
        (const float4*)Wq, (uint2*)p_Wqhi, (uint2*)p_Wqlo, nW4,
        (const float4*)Wk, (uint2*)p_Wkhi, (uint2*)p_Wklo, nW4,
        (const float4*)Wo, (uint2*)p_Wohi, (uint2*)p_Wolo, nW4);

    dim3 ggrid(D_MODEL / BN, NROWS / BM, 2);   // (8, 32, 2)
    qk_gemm_kernel<<<ggrid, 256, GSMEM2>>>(bq, bk);

    dim3 agrid(BATCH * NHEADS, SEQ / 128);     // (32, 16)
    attn_mma_kernel<<<agrid, 256, ASMEM>>>();

    dim3 ogrid(D_MODEL / BN, NROWS / BM, 1);   // (8, 32)
    out_gemm_kernel<<<ogrid, 256, GSMEM1>>>(bo, out);
}

// round 10
// speedup vs baseline: 1.7262x; 1.3223x over previous
#include <cuda_runtime.h>
#include <cuda_fp16.h>
#include <cstdint>

#define D_MODEL 1024
#define NHEADS  16
#define HDIM    64
#define BATCH   2
#define SEQ     2048
#define NROWS   (BATCH * SEQ)     // 4096
#define KDIM    D_MODEL

// softmax scale folded into Q projection: 1/sqrt(64) * log2(e)
#define QK_SCALE 0.1803368801111244f

// ---------------------------------------------------------------------------
// Scratch (device globals)
// ---------------------------------------------------------------------------
__device__ __half g_Hhi [NROWS * D_MODEL];   // also V in attention
__device__ __half g_Qh  [NROWS * D_MODEL];
__device__ __half g_Kh  [NROWS * D_MODEL];
__device__ __half g_AOh [NROWS * D_MODEL];
__device__ __half g_Wqhi[D_MODEL * D_MODEL];
__device__ __half g_Wqlo[D_MODEL * D_MODEL];
__device__ __half g_Wkhi[D_MODEL * D_MODEL];
__device__ __half g_Wklo[D_MODEL * D_MODEL];
__device__ __half g_Wohi[D_MODEL * D_MODEL];

// ---------------------------------------------------------------------------
// helpers
// ---------------------------------------------------------------------------
__device__ __forceinline__ uint32_t smem_to_u32(const void* p) {
    uint32_t a;
    asm("{ .reg .u64 t; cvta.to.shared.u64 t, %1; cvt.u32.u64 %0, t; }"
        : "=r"(a) : "l"(p));
    return a;
}
__device__ __forceinline__ void ldsm_x4(uint32_t& r0, uint32_t& r1,
                                        uint32_t& r2, uint32_t& r3, uint32_t addr) {
    asm volatile("ldmatrix.sync.aligned.m8n8.x4.shared.b16 {%0,%1,%2,%3}, [%4];"
                 : "=r"(r0), "=r"(r1), "=r"(r2), "=r"(r3) : "r"(addr));
}
__device__ __forceinline__ void ldsm_x4_t(uint32_t& r0, uint32_t& r1,
                                          uint32_t& r2, uint32_t& r3, uint32_t addr) {
    asm volatile("ldmatrix.sync.aligned.m8n8.x4.trans.shared.b16 {%0,%1,%2,%3}, [%4];"
                 : "=r"(r0), "=r"(r1), "=r"(r2), "=r"(r3) : "r"(addr));
}
__device__ __forceinline__ void mma16816(float* c, const uint32_t* a,
                                         const uint32_t* b) {
    asm volatile(
        "mma.sync.aligned.m16n8k16.row.col.f32.f16.f16.f32 "
        "{%0,%1,%2,%3}, {%4,%5,%6,%7}, {%8,%9}, {%0,%1,%2,%3};"
        : "+f"(c[0]), "+f"(c[1]), "+f"(c[2]), "+f"(c[3])
        : "r"(a[0]), "r"(a[1]), "r"(a[2]), "r"(a[3]), "r"(b[0]), "r"(b[1]));
}
__device__ __forceinline__ float ex2f(float x) {
    float r;
    asm("ex2.approx.ftz.f32 %0, %1;" : "=f"(r) : "f"(x));
    return r;
}
__device__ __forceinline__ uint32_t packh2(float a, float b) {
    __half2 t = __floats2half2_rn(a, b);
    return *(uint32_t*)&t;
}
__device__ __forceinline__ void cp16(uint32_t smem, const void* g) {
    asm volatile("cp.async.cg.shared.global [%0], [%1], 16;"
                 :: "r"(smem), "l"(g) : "memory");
}
#define CP_COMMIT() asm volatile("cp.async.commit_group;" ::: "memory")
#define CP_WAIT0()  asm volatile("cp.async.wait_group 0;" ::: "memory")
#define CP_WAIT1()  asm volatile("cp.async.wait_group 1;" ::: "memory")

// ---------------------------------------------------------------------------
// fp32 -> fp16 hi (+ optional lo) split, 4 tensors in one launch
// ---------------------------------------------------------------------------
__device__ __forceinline__ void split4_do(const float4* src, uint2* hi, uint2* lo, int i)
{
    float4 v = src[i];
    __half h0 = __float2half_rn(v.x), h1 = __float2half_rn(v.y);
    __half h2 = __float2half_rn(v.z), h3 = __float2half_rn(v.w);
    hi[i] = make_uint2(
        (uint32_t)__half_as_ushort(h0) | ((uint32_t)__half_as_ushort(h1) << 16),
        (uint32_t)__half_as_ushort(h2) | ((uint32_t)__half_as_ushort(h3) << 16));
    if (lo) {
        float r0 = v.x - __half2float(h0), r1 = v.y - __half2float(h1);
        float r2 = v.z - __half2float(h2), r3 = v.w - __half2float(h3);
        lo[i] = make_uint2(packh2(r0, r1), packh2(r2, r3));
    }
}

__global__ __launch_bounds__(256)
void split4_kernel(const float4* s0, uint2* h0, uint2* l0, int n0,
                   const float4* s1, uint2* h1, uint2* l1, int n1,
                   const float4* s2, uint2* h2, uint2* l2, int n2,
                   const float4* s3, uint2* h3, uint2* l3, int n3)
{
    int i = blockIdx.x * blockDim.x + threadIdx.x;
    if (i < n0) { split4_do(s0, h0, l0, i); return; }
    i -= n0;
    if (i < n1) { split4_do(s1, h1, l1, i); return; }
    i -= n1;
    if (i < n2) { split4_do(s2, h2, l2, i); return; }
    i -= n2;
    if (i < n3) { split4_do(s3, h3, l3, i); }
}

// ---------------------------------------------------------------------------
// HMMA GEMM, PASSES-template: C = Ahi*Whi (+ Ahi*Wlo if PASSES==2) + bias.
// CTA 128x128, BK=64, 256 threads (8 warps), 3-stage cp.async pipeline.
// ---------------------------------------------------------------------------
#define BM 128
#define BN 128
#define BKK 64
#define LDT 72                     // 144 B row (9 x 16B) -> LDSM conflict-free
#define GTILE (BM * LDT * 2)       // 18432 B per array
#define GNIT  (KDIM / BKK)         // 16

template <int PASSES>
__device__ __forceinline__ void gemm_core(
    const __half* __restrict__ Ahi,
    const __half* __restrict__ Whi, const __half* __restrict__ Wlo,
    const float* __restrict__ bias, float scale,
    float* __restrict__ Cf, __half* __restrict__ Ch)
{
    constexpr int NARR = 1 + PASSES;
    constexpr int GST  = NARR * GTILE;

    extern __shared__ char dsm[];
    __shared__ float s_bias[BN];

    const int tid = threadIdx.x;
    const int wid = tid >> 5;
    const int lid = tid & 31;
    const int wm  = wid & 1;
    const int wn  = wid >> 1;
    const int m0  = blockIdx.y * BM;
    const int n0  = blockIdx.x * BN;

    if (tid < BN) s_bias[tid] = bias[n0 + tid];

    const int lr     = lid & 7;
    const int half2_ = (lid >> 3) & 1;
    const int kh     = (lid >> 4) & 1;
    const int mbase  = wm * 64;
    const int nbase  = wn * 32;

    const uint32_t smem_base = smem_to_u32(dsm);

    float acc[4][4][4];
#pragma unroll
    for (int i = 0; i < 4; i++)
#pragma unroll
        for (int j = 0; j < 4; j++)
#pragma unroll
            for (int c = 0; c < 4; c++) acc[i][j][c] = 0.0f;

    auto load_stage = [&](int k0, int s) {
        uint32_t sb = smem_base + s * GST;
#pragma unroll
        for (int it = 0; it < 4 * NARR; it++) {
            int e    = tid + it * 256;
            int arr  = e >> 10;
            int rem  = e & 1023;
            int row  = rem >> 3;
            int c    = rem & 7;
            const __half* g;
            if (arr == 0)      g = Ahi + (size_t)(m0 + row) * KDIM + k0 + c * 8;
            else if (arr == 1) g = Whi + (size_t)(n0 + row) * KDIM + k0 + c * 8;
            else               g = Wlo + (size_t)(n0 + row) * KDIM + k0 + c * 8;
            cp16(sb + arr * GTILE + row * (LDT * 2) + c * 16, g);
        }
        CP_COMMIT();
    };

    load_stage(0, 0);
    load_stage(BKK, 1);

    for (int i = 0; i < GNIT; i++) {
        if (i + 1 < GNIT) { CP_WAIT1(); } else { CP_WAIT0(); }
        __syncthreads();
        if (i + 2 < GNIT) load_stage((i + 2) * BKK, (i + 2) % 3);

        const uint32_t sb   = smem_base + (i % 3) * GST;
        const uint32_t uAhi = sb;
        const uint32_t uWhi = sb + GTILE;
        const uint32_t uWlo = sb + 2 * GTILE;

#pragma unroll
        for (int ks = 0; ks < 4; ks++) {
            const int kcol = ks * 16 + kh * 8;

            uint32_t ahi[4][4];
#pragma unroll
            for (int mt = 0; mt < 4; mt++) {
                int row = mbase + mt * 16 + lr + 8 * half2_;
                ldsm_x4(ahi[mt][0], ahi[mt][1], ahi[mt][2], ahi[mt][3],
                        uAhi + (uint32_t)(row * LDT + kcol) * 2);
            }
            uint32_t bhi[4][2], blo[4][2];
#pragma unroll
            for (int ntp = 0; ntp < 2; ntp++) {
                int row = nbase + ntp * 16 + lr + 8 * half2_;
                uint32_t r0, r1, r2, r3;
                ldsm_x4(r0, r1, r2, r3, uWhi + (uint32_t)(row * LDT + kcol) * 2);
                bhi[ntp * 2 + 0][0] = r0; bhi[ntp * 2 + 0][1] = r2;
                bhi[ntp * 2 + 1][0] = r1; bhi[ntp * 2 + 1][1] = r3;
                if (PASSES == 2) {
                    ldsm_x4(r0, r1, r2, r3, uWlo + (uint32_t)(row * LDT + kcol) * 2);
                    blo[ntp * 2 + 0][0] = r0; blo[ntp * 2 + 0][1] = r2;
                    blo[ntp * 2 + 1][0] = r1; blo[ntp * 2 + 1][1] = r3;
                }
            }
#pragma unroll
            for (int mt = 0; mt < 4; mt++)
#pragma unroll
                for (int nt = 0; nt < 4; nt++)
                    mma16816(acc[mt][nt], ahi[mt], bhi[nt]);
            if (PASSES == 2) {
#pragma unroll
                for (int mt = 0; mt < 4; mt++)
#pragma unroll
                    for (int nt = 0; nt < 4; nt++)
                        mma16816(acc[mt][nt], ahi[mt], blo[nt]);
            }
        }
    }

    const int erow = lid >> 2;
    const int ecol = (lid & 3) * 2;
#pragma unroll
    for (int mt = 0; mt < 4; mt++) {
#pragma unroll
        for (int nt = 0; nt < 4; nt++) {
            int gm = m0 + mbase + mt * 16 + erow;
            int nc = nbase + nt * 8 + ecol;
            int gn = n0 + nc;
            float v0 = (acc[mt][nt][0] + s_bias[nc])     * scale;
            float v1 = (acc[mt][nt][1] + s_bias[nc + 1]) * scale;
            float v2 = (acc[mt][nt][2] + s_bias[nc])     * scale;
            float v3 = (acc[mt][nt][3] + s_bias[nc + 1]) * scale;
            if (Ch) {
                *(uint32_t*)&Ch[(size_t)gm * D_MODEL + gn]       = packh2(v0, v1);
                *(uint32_t*)&Ch[(size_t)(gm + 8) * D_MODEL + gn] = packh2(v2, v3);
            } else {
                *(float2*)&Cf[(size_t)gm * D_MODEL + gn]       = make_float2(v0, v1);
                *(float2*)&Cf[(size_t)(gm + 8) * D_MODEL + gn] = make_float2(v2, v3);
            }
        }
    }
}

__global__ __launch_bounds__(256, 1)
void qk_gemm_kernel(const float* __restrict__ bq, const float* __restrict__ bk)
{
    if (blockIdx.z == 0)
        gemm_core<2>(g_Hhi, g_Wqhi, g_Wqlo, bq, QK_SCALE, nullptr, g_Qh);
    else
        gemm_core<2>(g_Hhi, g_Wkhi, g_Wklo, bk, 1.0f, nullptr, g_Kh);
}

__global__ __launch_bounds__(256, 1)
void out_gemm_kernel(const float* __restrict__ bo, float* __restrict__ out)
{
    gemm_core<1>(g_AOh, g_Wohi, nullptr, bo, 1.0f, out, nullptr);
}

// ---------------------------------------------------------------------------
// HMMA flash attention: QK^T 1-pass (QhKh), PV 1-pass (P·Vh). 3-stage pipeline.
// grid (32 = B*NH, 16 = SEQ/128), 256 threads (8 warps), 128 q-rows per CTA.
// ---------------------------------------------------------------------------
#define SLDT 72                        // 144 B row
#define ATILE (64 * SLDT * 2)          // 9216 B per array
#define AST   (2 * ATILE)              // 18432 B per stage (Kh, Vh)
#define KTILES (SEQ / 64)              // 32

__global__ __launch_bounds__(256, 1)
void attn_mma_kernel()
{
    extern __shared__ char dsm[];
    __half* pool = (__half*)dsm;

    const int tid = threadIdx.x;
    const int wid = tid >> 5;
    const int lid = tid & 31;
    const int b   = blockIdx.x >> 4;
    const int h   = blockIdx.x & 15;
    const int q0  = blockIdx.y * 128;

    const int lr     = lid & 7;
    const int half2_ = (lid >> 3) & 1;
    const int kh     = (lid >> 4) & 1;

    const uint32_t smem_base = smem_to_u32(dsm);

    // ---- stage Q-hi tile (128 x 64) through stage-0 area, extract frags ----
#pragma unroll
    for (int i = 0; i < 4; i++) {
        int e   = tid + i * 256;            // 0..1023
        int row = e >> 3;
        int c   = e & 7;
        const __half* src = g_Qh
            + (size_t)(b * SEQ + q0 + row) * D_MODEL + h * HDIM + c * 8;
        *(uint4*)(pool + row * SLDT + c * 8) = *(const uint4*)src;
    }
    __syncthreads();

    uint32_t qh[4][4];
    {
        const int wr = wid * 16;
#pragma unroll
        for (int kc = 0; kc < 4; kc++) {
            int row = wr + lr + 8 * half2_;
            int col = kc * 16 + kh * 8;
            ldsm_x4(qh[kc][0], qh[kc][1], qh[kc][2], qh[kc][3],
                    smem_base + (uint32_t)(row * SLDT + col) * 2);
        }
    }
    __syncthreads();

    float oacc[8][4];
#pragma unroll
    for (int nt = 0; nt < 8; nt++)
#pragma unroll
        for (int c = 0; c < 4; c++) oacc[nt][c] = 0.0f;
    float mx0 = -1e30f, mx1 = -1e30f, l0 = 0.0f, l1 = 0.0f;

    auto load_stage = [&](int kt, int s) {
        const int kb = kt * 64;
        uint32_t sb = smem_base + s * AST;
#pragma unroll
        for (int i = 0; i < 4; i++) {
            int arr = i >> 1;                       // 0 Kh, 1 Vh
            int rem = ((i & 1) << 8) + tid;
            int row = rem >> 3;
            int c   = rem & 7;
            const __half* g = (arr == 0 ? g_Kh : g_Hhi)
                + (size_t)(b * SEQ + kb + row) * D_MODEL + h * HDIM + c * 8;
            cp16(sb + arr * ATILE + row * (SLDT * 2) + c * 16, g);
        }
        CP_COMMIT();
    };

    load_stage(0, 0);
    load_stage(1, 1);

    for (int kt = 0; kt < KTILES; kt++) {
        if (kt + 1 < KTILES) { CP_WAIT1(); } else { CP_WAIT0(); }
        __syncthreads();
        if (kt + 2 < KTILES) load_stage(kt + 2, (kt + 2) % 3);

        const uint32_t sb  = smem_base + (kt % 3) * AST;
        const uint32_t uKh = sb;
        const uint32_t uVh = sb + ATILE;

        // ---- S = Qh Kh^T (1-pass) ----
        float S[8][4];
#pragma unroll
        for (int nt = 0; nt < 8; nt++)
#pragma unroll
            for (int c = 0; c < 4; c++) S[nt][c] = 0.0f;

#pragma unroll
        for (int kc = 0; kc < 4; kc++) {
            uint32_t kbh[8][2];
#pragma unroll
            for (int ng = 0; ng < 4; ng++) {
                int row = ng * 16 + lr + 8 * half2_;
                int col = kc * 16 + kh * 8;
                uint32_t r0, r1, r2, r3;
                ldsm_x4(r0, r1, r2, r3, uKh + (uint32_t)(row * SLDT + col) * 2);
                kbh[ng * 2 + 0][0] = r0; kbh[ng * 2 + 0][1] = r2;
                kbh[ng * 2 + 1][0] = r1; kbh[ng * 2 + 1][1] = r3;
            }
#pragma unroll
            for (int nt = 0; nt < 8; nt++)
                mma16816(S[nt], qh[kc], kbh[nt]);
        }

        // ---- online softmax ----
        float tm0 = -1e30f, tm1 = -1e30f;
#pragma unroll
        for (int nt = 0; nt < 8; nt++) {
            tm0 = fmaxf(tm0, fmaxf(S[nt][0], S[nt][1]));
            tm1 = fmaxf(tm1, fmaxf(S[nt][2], S[nt][3]));
        }
        tm0 = fmaxf(tm0, __shfl_xor_sync(0xffffffffu, tm0, 1));
        tm0 = fmaxf(tm0, __shfl_xor_sync(0xffffffffu, tm0, 2));
        tm1 = fmaxf(tm1, __shfl_xor_sync(0xffffffffu, tm1, 1));
        tm1 = fmaxf(tm1, __shfl_xor_sync(0xffffffffu, tm1, 2));
        float mn0 = fmaxf(mx0, tm0), mn1 = fmaxf(mx1, tm1);
        float a0 = ex2f(mx0 - mn0), a1 = ex2f(mx1 - mn1);

        uint32_t pa[4][4];
        float rs0 = 0.0f, rs1 = 0.0f;
#pragma unroll
        for (int j = 0; j < 4; j++) {
#pragma unroll
            for (int sg = 0; sg < 2; sg++) {
                int t2 = j * 2 + sg;
                float p0 = ex2f(S[t2][0] - mn0);
                float p1 = ex2f(S[t2][1] - mn0);
                float p2 = ex2f(S[t2][2] - mn1);
                float p3 = ex2f(S[t2][3] - mn1);
                rs0 += p0 + p1;
                rs1 += p2 + p3;
                pa[j][sg * 2 + 0] = packh2(p0, p1);
                pa[j][sg * 2 + 1] = packh2(p2, p3);
            }
        }
        rs0 += __shfl_xor_sync(0xffffffffu, rs0, 1);
        rs0 += __shfl_xor_sync(0xffffffffu, rs0, 2);
        rs1 += __shfl_xor_sync(0xffffffffu, rs1, 1);
        rs1 += __shfl_xor_sync(0xffffffffu, rs1, 2);
        l0 = l0 * a0 + rs0;
        l1 = l1 * a1 + rs1;
        mx0 = mn0; mx1 = mn1;
#pragma unroll
        for (int nt = 0; nt < 8; nt++) {
            oacc[nt][0] *= a0; oacc[nt][1] *= a0;
            oacc[nt][2] *= a1; oacc[nt][3] *= a1;
        }

        // ---- O += P Vh (1-pass) ----
#pragma unroll
        for (int kc = 0; kc < 4; kc++) {
            uint32_t vbh[8][2];
#pragma unroll
            for (int dg = 0; dg < 4; dg++) {
                int rowk = kc * 16 + lr + 8 * half2_;
                int dimc = dg * 16 + kh * 8;
                uint32_t r0, r1, r2, r3;
                ldsm_x4_t(r0, r1, r2, r3, uVh + (uint32_t)(rowk * SLDT + dimc) * 2);
                vbh[dg * 2 + 0][0] = r0; vbh[dg * 2 + 0][1] = r1;
                vbh[dg * 2 + 1][0] = r2; vbh[dg * 2 + 1][1] = r3;
            }
#pragma unroll
            for (int nt = 0; nt < 8; nt++)
                mma16816(oacc[nt], pa[kc], vbh[nt]);
        }
    }

    // ---- epilogue ----
    const float inv0 = 1.0f / l0;
    const float inv1 = 1.0f / l1;
    const int gr  = b * SEQ + q0 + wid * 16 + (lid >> 2);
    const int col = h * HDIM + (lid & 3) * 2;
#pragma unroll
    for (int nt = 0; nt < 8; nt++) {
        int gc = col + nt * 8;
        float v0 = oacc[nt][0] * inv0, v1 = oacc[nt][1] * inv0;
        float v2 = oacc[nt][2] * inv1, v3 = oacc[nt][3] * inv1;
        *(uint32_t*)&g_AOh[(size_t)gr * D_MODEL + gc]       = packh2(v0, v1);
        *(uint32_t*)&g_AOh[(size_t)(gr + 8) * D_MODEL + gc] = packh2(v2, v3);
    }
}

// ---------------------------------------------------------------------------
extern "C" void kernel_launch(void* const* d_in, const int* in_sizes, int n_in,
                              void* d_out, int out_size)
{
    (void)in_sizes; (void)n_in; (void)out_size;
    const float* H  = (const float*)d_in[0];
    const float* Wq = (const float*)d_in[1];
    const float* bq = (const float*)d_in[2];
    const float* Wk = (const float*)d_in[3];
    const float* bk = (const float*)d_in[4];
    const float* Wo = (const float*)d_in[5];
    const float* bo = (const float*)d_in[6];
    float* out = (float*)d_out;

    void *p_Hhi;
    void *p_Wqhi, *p_Wqlo, *p_Wkhi, *p_Wklo, *p_Wohi;
    cudaGetSymbolAddress(&p_Hhi,  g_Hhi);
    cudaGetSymbolAddress(&p_Wqhi, g_Wqhi); cudaGetSymbolAddress(&p_Wqlo, g_Wqlo);
    cudaGetSymbolAddress(&p_Wkhi, g_Wkhi); cudaGetSymbolAddress(&p_Wklo, g_Wklo);
    cudaGetSymbolAddress(&p_Wohi, g_Wohi);

    const int GSMEM2 = 3 * (3 * GTILE);   // 165,888 B
    const int GSMEM1 = 3 * (2 * GTILE);   // 110,592 B
    const int ASMEM  = 3 * AST;           //  55,296 B

    cudaFuncSetAttribute(qk_gemm_kernel,
                         cudaFuncAttributeMaxDynamicSharedMemorySize, GSMEM2);
    cudaFuncSetAttribute(out_gemm_kernel,
                         cudaFuncAttributeMaxDynamicSharedMemorySize, GSMEM1);
    cudaFuncSetAttribute(attn_mma_kernel,
                         cudaFuncAttributeMaxDynamicSharedMemorySize, ASMEM);

    const int nH4 = NROWS * D_MODEL / 4;      // 1,048,576
    const int nW4 = D_MODEL * D_MODEL / 4;    // 262,144
    const int nTot = nH4 + 3 * nW4;           // 1,835,008

    split4_kernel<<<(nTot + 255) / 256, 256>>>(
        (const float4*)H,  (uint2*)p_Hhi,  nullptr,        nH4,
        (const float4*)Wq, (uint2*)p_Wqhi, (uint2*)p_Wqlo, nW4,
        (const float4*)Wk, (uint2*)p_Wkhi, (uint2*)p_Wklo, nW4,
        (const float4*)Wo, (uint2*)p_Wohi, nullptr,        nW4);

    dim3 ggrid(D_MODEL / BN, NROWS / BM, 2);   // (8, 32, 2)
    qk_gemm_kernel<<<ggrid, 256, GSMEM2>>>(bq, bk);

    dim3 agrid(BATCH * NHEADS, SEQ / 128);     // (32, 16)
    attn_mma_kernel<<<agrid, 256, ASMEM>>>();

    dim3 ogrid(D_MODEL / BN, NROWS / BM, 1);   // (8, 32)
    out_gemm_kernel<<<ogrid, 256, GSMEM1>>>(bo, out);
}

// round 11
// speedup vs baseline: 2.1953x; 1.2717x over previous
#include <cuda_runtime.h>
#include <cuda_fp16.h>
#include <cstdint>

#define D_MODEL 1024
#define NHEADS  16
#define HDIM    64
#define BATCH   2
#define SEQ     2048
#define NROWS   (BATCH * SEQ)     // 4096
#define KDIM    D_MODEL

// softmax scale folded into Q projection: 1/sqrt(64) * log2(e)
#define QK_SCALE 0.1803368801111244f

// ---------------------------------------------------------------------------
// Scratch (device globals) — pure fp16 now
// ---------------------------------------------------------------------------
__device__ __half g_Hh [NROWS * D_MODEL];   // H, also V in attention
__device__ __half g_Qh [NROWS * D_MODEL];
__device__ __half g_Kh [NROWS * D_MODEL];
__device__ __half g_AOh[NROWS * D_MODEL];
__device__ __half g_Wqh[D_MODEL * D_MODEL];
__device__ __half g_Wkh[D_MODEL * D_MODEL];
__device__ __half g_Woh[D_MODEL * D_MODEL];

// ---------------------------------------------------------------------------
// helpers
// ---------------------------------------------------------------------------
__device__ __forceinline__ uint32_t smem_to_u32(const void* p) {
    uint32_t a;
    asm("{ .reg .u64 t; cvta.to.shared.u64 t, %1; cvt.u32.u64 %0, t; }"
        : "=r"(a) : "l"(p));
    return a;
}
__device__ __forceinline__ void ldsm_x4(uint32_t& r0, uint32_t& r1,
                                        uint32_t& r2, uint32_t& r3, uint32_t addr) {
    asm volatile("ldmatrix.sync.aligned.m8n8.x4.shared.b16 {%0,%1,%2,%3}, [%4];"
                 : "=r"(r0), "=r"(r1), "=r"(r2), "=r"(r3) : "r"(addr));
}
__device__ __forceinline__ void ldsm_x4_t(uint32_t& r0, uint32_t& r1,
                                          uint32_t& r2, uint32_t& r3, uint32_t addr) {
    asm volatile("ldmatrix.sync.aligned.m8n8.x4.trans.shared.b16 {%0,%1,%2,%3}, [%4];"
                 : "=r"(r0), "=r"(r1), "=r"(r2), "=r"(r3) : "r"(addr));
}
__device__ __forceinline__ void mma16816(float* c, const uint32_t* a,
                                         const uint32_t* b) {
    asm volatile(
        "mma.sync.aligned.m16n8k16.row.col.f32.f16.f16.f32 "
        "{%0,%1,%2,%3}, {%4,%5,%6,%7}, {%8,%9}, {%0,%1,%2,%3};"
        : "+f"(c[0]), "+f"(c[1]), "+f"(c[2]), "+f"(c[3])
        : "r"(a[0]), "r"(a[1]), "r"(a[2]), "r"(a[3]), "r"(b[0]), "r"(b[1]));
}
__device__ __forceinline__ float ex2f(float x) {
    float r;
    asm("ex2.approx.ftz.f32 %0, %1;" : "=f"(r) : "f"(x));
    return r;
}
__device__ __forceinline__ uint32_t packh2(float a, float b) {
    __half2 t = __floats2half2_rn(a, b);
    return *(uint32_t*)&t;
}
__device__ __forceinline__ void cp16(uint32_t smem, const void* g) {
    asm volatile("cp.async.cg.shared.global [%0], [%1], 16;"
                 :: "r"(smem), "l"(g) : "memory");
}
#define CP_COMMIT() asm volatile("cp.async.commit_group;" ::: "memory")
#define CP_WAIT0()  asm volatile("cp.async.wait_group 0;" ::: "memory")
#define CP_WAIT1()  asm volatile("cp.async.wait_group 1;" ::: "memory")

// ---------------------------------------------------------------------------
// fp32 -> fp16 cast, 4 tensors in one launch
// ---------------------------------------------------------------------------
__device__ __forceinline__ void cast4_do(const float4* src, uint2* hi, int i)
{
    float4 v = src[i];
    hi[i] = make_uint2(packh2(v.x, v.y), packh2(v.z, v.w));
}

__global__ __launch_bounds__(256)
void cast4_kernel(const float4* s0, uint2* h0, int n0,
                  const float4* s1, uint2* h1, int n1,
                  const float4* s2, uint2* h2, int n2,
                  const float4* s3, uint2* h3, int n3)
{
    int i = blockIdx.x * blockDim.x + threadIdx.x;
    if (i < n0) { cast4_do(s0, h0, i); return; }
    i -= n0;
    if (i < n1) { cast4_do(s1, h1, i); return; }
    i -= n1;
    if (i < n2) { cast4_do(s2, h2, i); return; }
    i -= n2;
    if (i < n3) { cast4_do(s3, h3, i); }
}

// ---------------------------------------------------------------------------
// HMMA GEMM (1-pass fp16): C = A*W^T + bias.
// CTA 128x128, BK=64, 256 threads (8 warps), 3-stage cp.async pipeline.
// ---------------------------------------------------------------------------
#define BM 128
#define BN 128
#define BKK 64
#define LDT 72                     // 144 B row (9 x 16B) -> LDSM conflict-free
#define GTILE (BM * LDT * 2)       // 18432 B per array
#define GST   (2 * GTILE)          // A + W per stage
#define GNIT  (KDIM / BKK)         // 16

__device__ __forceinline__ void gemm_core(
    const __half* __restrict__ A, const __half* __restrict__ W,
    const float* __restrict__ bias, float scale,
    float* __restrict__ Cf, __half* __restrict__ Ch)
{
    extern __shared__ char dsm[];
    __shared__ float s_bias[BN];

    const int tid = threadIdx.x;
    const int wid = tid >> 5;
    const int lid = tid & 31;
    const int wm  = wid & 1;
    const int wn  = wid >> 1;
    const int m0  = blockIdx.y * BM;
    const int n0  = blockIdx.x * BN;

    if (tid < BN) s_bias[tid] = bias[n0 + tid];

    const int lr     = lid & 7;
    const int half2_ = (lid >> 3) & 1;
    const int kh     = (lid >> 4) & 1;
    const int mbase  = wm * 64;
    const int nbase  = wn * 32;

    const uint32_t smem_base = smem_to_u32(dsm);

    float acc[4][4][4];
#pragma unroll
    for (int i = 0; i < 4; i++)
#pragma unroll
        for (int j = 0; j < 4; j++)
#pragma unroll
            for (int c = 0; c < 4; c++) acc[i][j][c] = 0.0f;

    auto load_stage = [&](int k0, int s) {
        uint32_t sb = smem_base + s * GST;
#pragma unroll
        for (int it = 0; it < 8; it++) {
            int e    = tid + it * 256;      // 0..2047
            int arr  = e >> 10;             // 0 A, 1 W
            int rem  = e & 1023;
            int row  = rem >> 3;
            int c    = rem & 7;
            const __half* g = (arr == 0)
                ? A + (size_t)(m0 + row) * KDIM + k0 + c * 8
                : W + (size_t)(n0 + row) * KDIM + k0 + c * 8;
            cp16(sb + arr * GTILE + row * (LDT * 2) + c * 16, g);
        }
        CP_COMMIT();
    };

    load_stage(0, 0);
    load_stage(BKK, 1);

    for (int i = 0; i < GNIT; i++) {
        if (i + 1 < GNIT) { CP_WAIT1(); } else { CP_WAIT0(); }
        __syncthreads();
        if (i + 2 < GNIT) load_stage((i + 2) * BKK, (i + 2) % 3);

        const uint32_t sb = smem_base + (i % 3) * GST;
        const uint32_t uA = sb;
        const uint32_t uW = sb + GTILE;

#pragma unroll
        for (int ks = 0; ks < 4; ks++) {
            const int kcol = ks * 16 + kh * 8;

            uint32_t af[4][4];
#pragma unroll
            for (int mt = 0; mt < 4; mt++) {
                int row = mbase + mt * 16 + lr + 8 * half2_;
                ldsm_x4(af[mt][0], af[mt][1], af[mt][2], af[mt][3],
                        uA + (uint32_t)(row * LDT + kcol) * 2);
            }
            uint32_t bf[4][2];
#pragma unroll
            for (int ntp = 0; ntp < 2; ntp++) {
                int row = nbase + ntp * 16 + lr + 8 * half2_;
                uint32_t r0, r1, r2, r3;
                ldsm_x4(r0, r1, r2, r3, uW + (uint32_t)(row * LDT + kcol) * 2);
                bf[ntp * 2 + 0][0] = r0; bf[ntp * 2 + 0][1] = r2;
                bf[ntp * 2 + 1][0] = r1; bf[ntp * 2 + 1][1] = r3;
            }
#pragma unroll
            for (int mt = 0; mt < 4; mt++)
#pragma unroll
                for (int nt = 0; nt < 4; nt++)
                    mma16816(acc[mt][nt], af[mt], bf[nt]);
        }
    }

    const int erow = lid >> 2;
    const int ecol = (lid & 3) * 2;
#pragma unroll
    for (int mt = 0; mt < 4; mt++) {
#pragma unroll
        for (int nt = 0; nt < 4; nt++) {
            int gm = m0 + mbase + mt * 16 + erow;
            int nc = nbase + nt * 8 + ecol;
            int gn = n0 + nc;
            float v0 = (acc[mt][nt][0] + s_bias[nc])     * scale;
            float v1 = (acc[mt][nt][1] + s_bias[nc + 1]) * scale;
            float v2 = (acc[mt][nt][2] + s_bias[nc])     * scale;
            float v3 = (acc[mt][nt][3] + s_bias[nc + 1]) * scale;
            if (Ch) {
                *(uint32_t*)&Ch[(size_t)gm * D_MODEL + gn]       = packh2(v0, v1);
                *(uint32_t*)&Ch[(size_t)(gm + 8) * D_MODEL + gn] = packh2(v2, v3);
            } else {
                *(float2*)&Cf[(size_t)gm * D_MODEL + gn]       = make_float2(v0, v1);
                *(float2*)&Cf[(size_t)(gm + 8) * D_MODEL + gn] = make_float2(v2, v3);
            }
        }
    }
}

__global__ __launch_bounds__(256, 1)
void qk_gemm_kernel(const float* __restrict__ bq, const float* __restrict__ bk)
{
    if (blockIdx.z == 0)
        gemm_core(g_Hh, g_Wqh, bq, QK_SCALE, nullptr, g_Qh);
    else
        gemm_core(g_Hh, g_Wkh, bk, 1.0f, nullptr, g_Kh);
}

__global__ __launch_bounds__(256, 1)
void out_gemm_kernel(const float* __restrict__ bo, float* __restrict__ out)
{
    gemm_core(g_AOh, g_Woh, bo, 1.0f, out, nullptr);
}

// ---------------------------------------------------------------------------
// HMMA flash attention (1-pass fp16 QK^T and PV). 3-stage cp.async pipeline.
// grid (32 = B*NH, 16 = SEQ/128), 256 threads (8 warps), 128 q-rows per CTA.
// ---------------------------------------------------------------------------
#define SLDT 72                        // 144 B row
#define ATILE (64 * SLDT * 2)          // 9216 B per array
#define AST   (2 * ATILE)              // 18432 B per stage (K, V)
#define KTILES (SEQ / 64)              // 32

__global__ __launch_bounds__(256, 1)
void attn_mma_kernel()
{
    extern __shared__ char dsm[];
    __half* pool = (__half*)dsm;

    const int tid = threadIdx.x;
    const int wid = tid >> 5;
    const int lid = tid & 31;
    const int b   = blockIdx.x >> 4;
    const int h   = blockIdx.x & 15;
    const int q0  = blockIdx.y * 128;

    const int lr     = lid & 7;
    const int half2_ = (lid >> 3) & 1;
    const int kh     = (lid >> 4) & 1;

    const uint32_t smem_base = smem_to_u32(dsm);

    // ---- stage Q tile (128 x 64) through stage-0 area, extract frags ----
#pragma unroll
    for (int i = 0; i < 4; i++) {
        int e   = tid + i * 256;            // 0..1023
        int row = e >> 3;
        int c   = e & 7;
        const __half* src = g_Qh
            + (size_t)(b * SEQ + q0 + row) * D_MODEL + h * HDIM + c * 8;
        *(uint4*)(pool + row * SLDT + c * 8) = *(const uint4*)src;
    }
    __syncthreads();

    uint32_t qh[4][4];
    {
        const int wr = wid * 16;
#pragma unroll
        for (int kc = 0; kc < 4; kc++) {
            int row = wr + lr + 8 * half2_;
            int col = kc * 16 + kh * 8;
            ldsm_x4(qh[kc][0], qh[kc][1], qh[kc][2], qh[kc][3],
                    smem_base + (uint32_t)(row * SLDT + col) * 2);
        }
    }
    __syncthreads();

    float oacc[8][4];
#pragma unroll
    for (int nt = 0; nt < 8; nt++)
#pragma unroll
        for (int c = 0; c < 4; c++) oacc[nt][c] = 0.0f;
    float mx0 = -1e30f, mx1 = -1e30f, l0 = 0.0f, l1 = 0.0f;

    auto load_stage = [&](int kt, int s) {
        const int kb = kt * 64;
        uint32_t sb = smem_base + s * AST;
#pragma unroll
        for (int i = 0; i < 4; i++) {
            int arr = i >> 1;                       // 0 K, 1 V
            int rem = ((i & 1) << 8) + tid;
            int row = rem >> 3;
            int c   = rem & 7;
            const __half* g = (arr == 0 ? g_Kh : g_Hh)
                + (size_t)(b * SEQ + kb + row) * D_MODEL + h * HDIM + c * 8;
            cp16(sb + arr * ATILE + row * (SLDT * 2) + c * 16, g);
        }
        CP_COMMIT();
    };

    load_stage(0, 0);
    load_stage(1, 1);

    for (int kt = 0; kt < KTILES; kt++) {
        if (kt + 1 < KTILES) { CP_WAIT1(); } else { CP_WAIT0(); }
        __syncthreads();
        if (kt + 2 < KTILES) load_stage(kt + 2, (kt + 2) % 3);

        const uint32_t sb = smem_base + (kt % 3) * AST;
        const uint32_t uK = sb;
        const uint32_t uV = sb + ATILE;

        // ---- S = Q K^T ----
        float S[8][4];
#pragma unroll
        for (int nt = 0; nt < 8; nt++)
#pragma unroll
            for (int c = 0; c < 4; c++) S[nt][c] = 0.0f;

#pragma unroll
        for (int kc = 0; kc < 4; kc++) {
            uint32_t kb_[8][2];
#pragma unroll
            for (int ng = 0; ng < 4; ng++) {
                int row = ng * 16 + lr + 8 * half2_;
                int col = kc * 16 + kh * 8;
                uint32_t r0, r1, r2, r3;
                ldsm_x4(r0, r1, r2, r3, uK + (uint32_t)(row * SLDT + col) * 2);
                kb_[ng * 2 + 0][0] = r0; kb_[ng * 2 + 0][1] = r2;
                kb_[ng * 2 + 1][0] = r1; kb_[ng * 2 + 1][1] = r3;
            }
#pragma unroll
            for (int nt = 0; nt < 8; nt++)
                mma16816(S[nt], qh[kc], kb_[nt]);
        }

        // ---- online softmax ----
        float tm0 = -1e30f, tm1 = -1e30f;
#pragma unroll
        for (int nt = 0; nt < 8; nt++) {
            tm0 = fmaxf(tm0, fmaxf(S[nt][0], S[nt][1]));
            tm1 = fmaxf(tm1, fmaxf(S[nt][2], S[nt][3]));
        }
        tm0 = fmaxf(tm0, __shfl_xor_sync(0xffffffffu, tm0, 1));
        tm0 = fmaxf(tm0, __shfl_xor_sync(0xffffffffu, tm0, 2));
        tm1 = fmaxf(tm1, __shfl_xor_sync(0xffffffffu, tm1, 1));
        tm1 = fmaxf(tm1, __shfl_xor_sync(0xffffffffu, tm1, 2));
        float mn0 = fmaxf(mx0, tm0), mn1 = fmaxf(mx1, tm1);
        float a0 = ex2f(mx0 - mn0), a1 = ex2f(mx1 - mn1);

        uint32_t pa[4][4];
        float rs0 = 0.0f, rs1 = 0.0f;
#pragma unroll
        for (int j = 0; j < 4; j++) {
#pragma unroll
            for (int sg = 0; sg < 2; sg++) {
                int t2 = j * 2 + sg;
                float p0 = ex2f(S[t2][0] - mn0);
                float p1 = ex2f(S[t2][1] - mn0);
                float p2 = ex2f(S[t2][2] - mn1);
                float p3 = ex2f(S[t2][3] - mn1);
                rs0 += p0 + p1;
                rs1 += p2 + p3;
                pa[j][sg * 2 + 0] = packh2(p0, p1);
                pa[j][sg * 2 + 1] = packh2(p2, p3);
            }
        }
        rs0 += __shfl_xor_sync(0xffffffffu, rs0, 1);
        rs0 += __shfl_xor_sync(0xffffffffu, rs0, 2);
        rs1 += __shfl_xor_sync(0xffffffffu, rs1, 1);
        rs1 += __shfl_xor_sync(0xffffffffu, rs1, 2);
        l0 = l0 * a0 + rs0;
        l1 = l1 * a1 + rs1;
        mx0 = mn0; mx1 = mn1;
#pragma unroll
        for (int nt = 0; nt < 8; nt++) {
            oacc[nt][0] *= a0; oacc[nt][1] *= a0;
            oacc[nt][2] *= a1; oacc[nt][3] *= a1;
        }

        // ---- O += P V ----
#pragma unroll
        for (int kc = 0; kc < 4; kc++) {
            uint32_t vb[8][2];
#pragma unroll
            for (int dg = 0; dg < 4; dg++) {
                int rowk = kc * 16 + lr + 8 * half2_;
                int dimc = dg * 16 + kh * 8;
                uint32_t r0, r1, r2, r3;
                ldsm_x4_t(r0, r1, r2, r3, uV + (uint32_t)(rowk * SLDT + dimc) * 2);
                vb[dg * 2 + 0][0] = r0; vb[dg * 2 + 0][1] = r1;
                vb[dg * 2 + 1][0] = r2; vb[dg * 2 + 1][1] = r3;
            }
#pragma unroll
            for (int nt = 0; nt < 8; nt++)
                mma16816(oacc[nt], pa[kc], vb[nt]);
        }
    }

    // ---- epilogue ----
    const float inv0 = 1.0f / l0;
    const float inv1 = 1.0f / l1;
    const int gr  = b * SEQ + q0 + wid * 16 + (lid >> 2);
    const int col = h * HDIM + (lid & 3) * 2;
#pragma unroll
    for (int nt = 0; nt < 8; nt++) {
        int gc = col + nt * 8;
        float v0 = oacc[nt][0] * inv0, v1 = oacc[nt][1] * inv0;
        float v2 = oacc[nt][2] * inv1, v3 = oacc[nt][3] * inv1;
        *(uint32_t*)&g_AOh[(size_t)gr * D_MODEL + gc]       = packh2(v0, v1);
        *(uint32_t*)&g_AOh[(size_t)(gr + 8) * D_MODEL + gc] = packh2(v2, v3);
    }
}

// ---------------------------------------------------------------------------
extern "C" void kernel_launch(void* const* d_in, const int* in_sizes, int n_in,
                              void* d_out, int out_size)
{
    (void)in_sizes; (void)n_in; (void)out_size;
    const float* H  = (const float*)d_in[0];
    const float* Wq = (const float*)d_in[1];
    const float* bq = (const float*)d_in[2];
    const float* Wk = (const float*)d_in[3];
    const float* bk = (const float*)d_in[4];
    const float* Wo = (const float*)d_in[5];
    const float* bo = (const float*)d_in[6];
    float* out = (float*)d_out;

    void *p_Hh, *p_Wqh, *p_Wkh, *p_Woh;
    cudaGetSymbolAddress(&p_Hh,  g_Hh);
    cudaGetSymbolAddress(&p_Wqh, g_Wqh);
    cudaGetSymbolAddress(&p_Wkh, g_Wkh);
    cudaGetSymbolAddress(&p_Woh, g_Woh);

    const int GSMEM = 3 * GST;    // 110,592 B
    const int ASMEM = 3 * AST;    //  55,296 B

    cudaFuncSetAttribute(qk_gemm_kernel,
                         cudaFuncAttributeMaxDynamicSharedMemorySize, GSMEM);
    cudaFuncSetAttribute(out_gemm_kernel,
                         cudaFuncAttributeMaxDynamicSharedMemorySize, GSMEM);
    cudaFuncSetAttribute(attn_mma_kernel,
                         cudaFuncAttributeMaxDynamicSharedMemorySize, ASMEM);

    const int nH4 = NROWS * D_MODEL / 4;      // 1,048,576
    const int nW4 = D_MODEL * D_MODEL / 4;    // 262,144
    const int nTot = nH4 + 3 * nW4;           // 1,835,008

    cast4_kernel<<<(nTot + 255) / 256, 256>>>(
        (const float4*)H,  (uint2*)p_Hh,  nH4,
        (const float4*)Wq, (uint2*)p_Wqh, nW4,
        (const float4*)Wk, (uint2*)p_Wkh, nW4,
        (const float4*)Wo, (uint2*)p_Woh, nW4);

    dim3 ggrid(D_MODEL / BN, NROWS / BM, 2);   // (8, 32, 2)
    qk_gemm_kernel<<<ggrid, 256, GSMEM>>>(bq, bk);

    dim3 agrid(BATCH * NHEADS, SEQ / 128);     // (32, 16)
    attn_mma_kernel<<<agrid, 256, ASMEM>>>();

    dim3 ogrid(D_MODEL / BN, NROWS / BM, 1);   // (8, 32)
    out_gemm_kernel<<<ogrid, 256, GSMEM>>>(bo, out);
}